// round 1
// baseline (speedup 1.0000x reference)
#include <cuda_runtime.h>

// Fixed problem shape
#define NB    2      // batch
#define CCH   64     // channels
#define LL    4096   // H*W
#define HEADS 2
#define DKK   64
#define DVV   32
#define NHH   4      // NB*HEADS

// Scratch (device globals: no allocation allowed)
__device__ float Qg[NHH * DKK * LL];            // [nh][dk][L]  (dk-major)
__device__ float Kg[NHH * DKK * LL];            // [nh][dk][L]
__device__ float Vg[NHH * DVV * LL];            // [nh][dv][L]
__device__ float Rg[NB * LL * (HEADS * DVV)];   // [n][l][h*DV+v]

// ---------------------------------------------------------------------------
// Kernel A: QKV projection (pointwise GEMM) + bias. Writes dk-major outputs.
// grid (L/64, NB), block 256.
// ---------------------------------------------------------------------------
__global__ __launch_bounds__(256) void qkv_kernel(
    const float* __restrict__ x,
    const float* __restrict__ Wq, const float* __restrict__ bq,
    const float* __restrict__ Wk, const float* __restrict__ bk,
    const float* __restrict__ Wv, const float* __restrict__ bv)
{
    __shared__ float xs[64][64];   // [c][l_local]
    __shared__ float ws[64][64];   // [row][c]
    const int lt = blockIdx.x, n = blockIdx.y;
    const int l0 = lt * 64;
    const int tid = threadIdx.x;
    const int j = tid & 63, rg = tid >> 6;

    #pragma unroll
    for (int t = 0; t < 16; t++) {
        int c = rg + 4 * t;
        xs[c][j] = x[((size_t)(n * CCH + c)) * LL + l0 + j];
    }

    for (int h = 0; h < HEADS; h++) {
        for (int sec = 0; sec < 3; sec++) {
            const float* W; const float* b; float* outg; int rows;
            if (sec == 0)      { W = Wq + h * DKK * CCH; b = bq + h * DKK; outg = Qg + (n * HEADS + h) * DKK * LL; rows = DKK; }
            else if (sec == 1) { W = Wk + h * DKK * CCH; b = bk + h * DKK; outg = Kg + (n * HEADS + h) * DKK * LL; rows = DKK; }
            else               { W = Wv + h * DVV * CCH; b = bv + h * DVV; outg = Vg + (n * HEADS + h) * DVV * LL; rows = DVV; }

            __syncthreads();  // also covers xs on first iteration
            for (int idx = tid; idx < rows * 64; idx += 256)
                ws[idx >> 6][idx & 63] = W[idx];
            __syncthreads();

            const int nchunk = rows / 16;
            for (int s4 = 0; s4 < nchunk; s4++) {
                const int base = s4 * 16 + rg * 4;   // warp-uniform
                float accs[4];
                #pragma unroll
                for (int u = 0; u < 4; u++) accs[u] = b[base + u];
                #pragma unroll
                for (int c = 0; c < 64; c++) {
                    float xv = xs[c][j];
                    #pragma unroll
                    for (int u = 0; u < 4; u++) accs[u] += ws[base + u][c] * xv;
                }
                #pragma unroll
                for (int u = 0; u < 4; u++)
                    outg[(size_t)(base + u) * LL + l0 + j] = accs[u];
            }
        }
    }
}

// ---------------------------------------------------------------------------
// Kernel B: in-place L2 normalize of Q and K columns (over dk, per (nh,l)).
// grid (L/64, NH, 2), block 256.
// ---------------------------------------------------------------------------
__global__ __launch_bounds__(256) void norm_kernel()
{
    __shared__ float part[4][64];
    __shared__ float scl[64];
    const int lt = blockIdx.x, nh = blockIdx.y, qk = blockIdx.z;
    float* ptr = (qk ? Kg : Qg) + (size_t)nh * DKK * LL + lt * 64;
    const int tid = threadIdx.x;
    const int j = tid & 63, c0 = tid >> 6;

    float v[16];
    float ss = 0.f;
    #pragma unroll
    for (int t = 0; t < 16; t++) {
        int d = c0 + 4 * t;
        v[t] = ptr[(size_t)d * LL + j];
        ss += v[t] * v[t];
    }
    part[c0][j] = ss;
    __syncthreads();
    if (tid < 64) {
        float s = part[0][tid] + part[1][tid] + part[2][tid] + part[3][tid];
        float nrm = sqrtf(s);
        scl[tid] = 1.0f / fmaxf(nrm, 1e-6f);
    }
    __syncthreads();
    const float sc = scl[j];
    #pragma unroll
    for (int t = 0; t < 16; t++) {
        int d = c0 + 4 * t;
        ptr[(size_t)d * LL + j] = v[t] * sc;
    }
}

// ---------------------------------------------------------------------------
// Kernel C: attention. Logits guaranteed in [-1,1] (cosine sim) -> no online
// max needed. Single pass over keys: O += exp(s)*V, Z += exp(s); R = O/Z.
// grid (L/64, NH), block 256, dynamic smem ~57.75KB.
// ---------------------------------------------------------------------------
#define VP 34   // Vs pitch (floats): float2-aligned, near-conflict-free
#define PP 68   // Ps pitch (floats): float4-aligned, conflict-free STS.128

__global__ __launch_bounds__(256) void attn_kernel()
{
    extern __shared__ float sm[];
    float* Qs = sm;                     // [64][64]  Q^T tile  (dk x q)
    float* Ks = sm + 4096;              // [64][64]  K^T tile  (dk x k)
    float* Vs = sm + 8192;              // [64][VP]  V tile    (k x dv)
    float* Ps = sm + 8192 + 64 * VP;    // [64][PP]  P tile    (q x k)
    float* Zs = Ps + 64 * PP;           // [64]      row sums

    const int nh = blockIdx.y;
    const int q0 = blockIdx.x * 64;
    const int tid = threadIdx.x;
    const int ty = tid >> 4, tx = tid & 15;   // S: 4q x 4k tile, PV: 4q x 2dv
    const int j = tid & 63, rg = tid >> 6;

    const float* Qp = Qg + (size_t)nh * DKK * LL;
    const float* Kp = Kg + (size_t)nh * DKK * LL;
    const float* Vp = Vg + (size_t)nh * DVV * LL;

    #pragma unroll
    for (int t = 0; t < 16; t++) {
        int d = rg + 4 * t;
        Qs[d * 64 + j] = Qp[(size_t)d * LL + q0 + j];
    }
    if (tid < 64) Zs[tid] = 0.f;

    float O[4][2] = {};

    for (int kt = 0; kt < LL / 64; kt++) {
        const int k0 = kt * 64;
        __syncthreads();   // protects Ks/Vs/Ps from previous iteration's readers
        #pragma unroll
        for (int t = 0; t < 16; t++) {
            int d = rg + 4 * t;
            Ks[d * 64 + j] = Kp[(size_t)d * LL + k0 + j];
        }
        #pragma unroll
        for (int t = 0; t < 8; t++) {
            int v = rg * 8 + t;
            Vs[j * VP + v] = Vp[(size_t)v * LL + k0 + j];
        }
        __syncthreads();

        // ---- S = Q^T K : 4x4 register tile per thread ----
        float acc[4][4] = {};
        #pragma unroll 8
        for (int kk = 0; kk < 64; kk++) {
            float4 a = *(const float4*)&Qs[kk * 64 + ty * 4];
            float4 b = *(const float4*)&Ks[kk * 64 + tx * 4];
            acc[0][0] += a.x * b.x; acc[0][1] += a.x * b.y; acc[0][2] += a.x * b.z; acc[0][3] += a.x * b.w;
            acc[1][0] += a.y * b.x; acc[1][1] += a.y * b.y; acc[1][2] += a.y * b.z; acc[1][3] += a.y * b.w;
            acc[2][0] += a.z * b.x; acc[2][1] += a.z * b.y; acc[2][2] += a.z * b.z; acc[2][3] += a.z * b.w;
            acc[3][0] += a.w * b.x; acc[3][1] += a.w * b.y; acc[3][2] += a.w * b.z; acc[3][3] += a.w * b.w;
        }

        // ---- P = exp(S), row partial sums ----
        float rs[4];
        #pragma unroll
        for (int i = 0; i < 4; i++) {
            rs[i] = 0.f;
            #pragma unroll
            for (int c = 0; c < 4; c++) {
                float p = __expf(acc[i][c]);
                acc[i][c] = p;
                rs[i] += p;
            }
        }
        #pragma unroll
        for (int i = 0; i < 4; i++) {
            rs[i] += __shfl_xor_sync(0xffffffffu, rs[i], 1);
            rs[i] += __shfl_xor_sync(0xffffffffu, rs[i], 2);
            rs[i] += __shfl_xor_sync(0xffffffffu, rs[i], 4);
            rs[i] += __shfl_xor_sync(0xffffffffu, rs[i], 8);
        }
        if (tx == 0) {   // unique writer per row
            #pragma unroll
            for (int i = 0; i < 4; i++) Zs[ty * 4 + i] += rs[i];
        }

        #pragma unroll
        for (int i = 0; i < 4; i++)
            *(float4*)&Ps[(ty * 4 + i) * PP + tx * 4] =
                make_float4(acc[i][0], acc[i][1], acc[i][2], acc[i][3]);
        __syncthreads();

        // ---- O += P V : thread = (4 queries) x (2 dv cols) ----
        #pragma unroll 4
        for (int kk = 0; kk < 64; kk += 4) {
            float4 a[4];
            #pragma unroll
            for (int i = 0; i < 4; i++)
                a[i] = *(const float4*)&Ps[(ty * 4 + i) * PP + kk];
            #pragma unroll
            for (int s = 0; s < 4; s++) {
                float2 bv2 = *(const float2*)&Vs[(kk + s) * VP + tx * 2];
                #pragma unroll
                for (int i = 0; i < 4; i++) {
                    float av = (s == 0) ? a[i].x : (s == 1) ? a[i].y : (s == 2) ? a[i].z : a[i].w;
                    O[i][0] += av * bv2.x;
                    O[i][1] += av * bv2.y;
                }
            }
        }
    }
    __syncthreads();

    const int n = nh >> 1, h = nh & 1;
    #pragma unroll
    for (int i = 0; i < 4; i++) {
        int q = ty * 4 + i;
        float inv = 1.0f / Zs[q];
        int l = q0 + q;
        float2 val = make_float2(O[i][0] * inv, O[i][1] * inv);
        *(float2*)&Rg[((size_t)n * LL + l) * (HEADS * DVV) + h * DVV + tx * 2] = val;
    }
}

// ---------------------------------------------------------------------------
// Kernel D: output projection + bias + residual.
// grid (L/64, NB), block 256.
// ---------------------------------------------------------------------------
__global__ __launch_bounds__(256) void out_kernel(
    const float* __restrict__ x,
    const float* __restrict__ Wm, const float* __restrict__ bm,
    float* __restrict__ out)
{
    __shared__ float Rst[64][65];   // [j][l_local], pitch 65 -> conflict-free
    __shared__ float wm[64][64];    // [c][j]
    const int lt = blockIdx.x, n = blockIdx.y;
    const int l0 = lt * 64;
    const int tid = threadIdx.x;
    const int j = tid & 63, rg = tid >> 6;

    #pragma unroll
    for (int t = 0; t < 16; t++) {
        int i = rg + 4 * t;
        Rst[j][i] = Rg[((size_t)n * LL + l0 + i) * 64 + j];
    }
    #pragma unroll
    for (int t = 0; t < 16; t++) {
        int c = rg + 4 * t;
        wm[c][j] = Wm[c * 64 + j];
    }
    __syncthreads();

    #pragma unroll
    for (int s4 = 0; s4 < 4; s4++) {
        const int base = s4 * 16 + rg * 4;   // warp-uniform
        float accs[4];
        #pragma unroll
        for (int u = 0; u < 4; u++) accs[u] = bm[base + u];
        #pragma unroll
        for (int jj = 0; jj < 64; jj++) {
            float rv = Rst[jj][j];
            #pragma unroll
            for (int u = 0; u < 4; u++) accs[u] += wm[base + u][jj] * rv;
        }
        #pragma unroll
        for (int u = 0; u < 4; u++) {
            int c = base + u;
            size_t idx = ((size_t)(n * CCH + c)) * LL + l0 + j;
            out[idx] = accs[u] + x[idx];
        }
    }
}

// ---------------------------------------------------------------------------
extern "C" void kernel_launch(void* const* d_in, const int* in_sizes, int n_in,
                              void* d_out, int out_size)
{
    const float* x  = (const float*)d_in[0];
    const float* Wq = (const float*)d_in[1];
    const float* bq = (const float*)d_in[2];
    const float* Wk = (const float*)d_in[3];
    const float* bk = (const float*)d_in[4];
    const float* Wv = (const float*)d_in[5];
    const float* bv = (const float*)d_in[6];
    const float* Wm = (const float*)d_in[7];
    const float* bm = (const float*)d_in[8];
    float* out = (float*)d_out;

    qkv_kernel<<<dim3(LL / 64, NB), 256>>>(x, Wq, bq, Wk, bk, Wv, bv);
    norm_kernel<<<dim3(LL / 64, NHH, 2), 256>>>();

    const size_t smB = (size_t)(4096 + 4096 + 64 * VP + 64 * PP + 64) * sizeof(float);
    cudaFuncSetAttribute(attn_kernel, cudaFuncAttributeMaxDynamicSharedMemorySize, (int)smB);
    attn_kernel<<<dim3(LL / 64, NHH), 256, smB>>>();

    out_kernel<<<dim3(LL / 64, NB), 256>>>(x, Wm, bm, out);
}

// round 4
// speedup vs baseline: 4.5293x; 4.5293x over previous
#include <cuda_runtime.h>
#include <cuda_fp16.h>
#include <cstdint>

// Fixed problem shape
#define NB    2
#define CCH   64
#define LL    4096
#define HEADS 2
#define DKK   64
#define DVV   32
#define NHH   4

// fp16 activations, l-major: [nh][L][dk]
__device__ __half Qh[NHH * LL * DKK];
__device__ __half Kh[NHH * LL * DKK];
__device__ __half Vh[NHH * LL * DVV];
__device__ float  Rg[NB * LL * (HEADS * DVV)];   // [n][l][h*DV+v]

// ---------------------------------------------------------------------------
// PTX helpers
// ---------------------------------------------------------------------------
__device__ __forceinline__ void ldsm4(uint32_t& r0, uint32_t& r1, uint32_t& r2, uint32_t& r3, uint32_t a) {
    asm volatile("ldmatrix.sync.aligned.m8n8.x4.shared.b16 {%0,%1,%2,%3}, [%4];\n"
                 : "=r"(r0), "=r"(r1), "=r"(r2), "=r"(r3) : "r"(a));
}
__device__ __forceinline__ void ldsm4t(uint32_t& r0, uint32_t& r1, uint32_t& r2, uint32_t& r3, uint32_t a) {
    asm volatile("ldmatrix.sync.aligned.m8n8.x4.trans.shared.b16 {%0,%1,%2,%3}, [%4];\n"
                 : "=r"(r0), "=r"(r1), "=r"(r2), "=r"(r3) : "r"(a));
}
__device__ __forceinline__ void mma16816(float* c, const uint32_t* a, uint32_t b0, uint32_t b1) {
    asm volatile("mma.sync.aligned.m16n8k16.row.col.f32.f16.f16.f32 "
                 "{%0,%1,%2,%3}, {%4,%5,%6,%7}, {%8,%9}, {%0,%1,%2,%3};\n"
                 : "+f"(c[0]), "+f"(c[1]), "+f"(c[2]), "+f"(c[3])
                 : "r"(a[0]), "r"(a[1]), "r"(a[2]), "r"(a[3]), "r"(b0), "r"(b1));
}
__device__ __forceinline__ uint32_t pack_h2(float x, float y) {
    __half2 h = __floats2half2_rn(x, y);
    return *(uint32_t*)&h;
}

// ---------------------------------------------------------------------------
// Kernel A: QKV projection + bias + (Q,K) L2-normalize + fp16 transpose-store.
// Output layout: [nh][l][dk] (dk contiguous). grid (64, NB), block 256.
// ---------------------------------------------------------------------------
__global__ __launch_bounds__(256) void qkvn_kernel(
    const float* __restrict__ x,
    const float* __restrict__ Wq, const float* __restrict__ bq,
    const float* __restrict__ Wk, const float* __restrict__ bk,
    const float* __restrict__ Wv, const float* __restrict__ bv)
{
    __shared__ float xs[64][64];     // [c][l_local]
    __shared__ float buf[64][65];    // weights, then staging [row][l]
    __shared__ float part[4][64];
    __shared__ float scl[64];
    const int lt = blockIdx.x, n = blockIdx.y;
    const int l0 = lt * 64;
    const int tid = threadIdx.x;
    const int j = tid & 63, rg = tid >> 6;

    #pragma unroll
    for (int t = 0; t < 16; t++) {
        int c = rg + 4 * t;
        xs[c][j] = x[((size_t)(n * CCH + c)) * LL + l0 + j];
    }

    for (int h = 0; h < HEADS; h++) {
        for (int sec = 0; sec < 3; sec++) {
            const float* W; const float* b; __half* outh; int rows; bool donorm;
            const int nh = n * HEADS + h;
            if (sec == 0)      { W = Wq + h * DKK * CCH; b = bq + h * DKK; outh = Qh + (size_t)nh * LL * DKK; rows = DKK; donorm = true; }
            else if (sec == 1) { W = Wk + h * DKK * CCH; b = bk + h * DKK; outh = Kh + (size_t)nh * LL * DKK; rows = DKK; donorm = true; }
            else               { W = Wv + h * DVV * CCH; b = bv + h * DVV; outh = Vh + (size_t)nh * LL * DVV; rows = DVV; donorm = false; }

            __syncthreads();   // also covers xs first time / buf reuse
            for (int idx = tid; idx < rows * 64; idx += 256)
                buf[idx >> 6][idx & 63] = W[idx];
            __syncthreads();

            // GEMM: this thread computes rows {s4*16 + rg*4 + u} at column j
            float acc[16];
            const int nchunk = rows / 16;
            for (int s4 = 0; s4 < nchunk; s4++) {
                const int base = s4 * 16 + rg * 4;
                float a0 = b[base], a1 = b[base + 1], a2 = b[base + 2], a3 = b[base + 3];
                #pragma unroll
                for (int c = 0; c < 64; c++) {
                    float xv = xs[c][j];
                    a0 += buf[base + 0][c] * xv;
                    a1 += buf[base + 1][c] * xv;
                    a2 += buf[base + 2][c] * xv;
                    a3 += buf[base + 3][c] * xv;
                }
                acc[s4 * 4 + 0] = a0; acc[s4 * 4 + 1] = a1;
                acc[s4 * 4 + 2] = a2; acc[s4 * 4 + 3] = a3;
            }
            __syncthreads();   // done reading weights; reuse buf as staging
            for (int s4 = 0; s4 < nchunk; s4++) {
                const int base = s4 * 16 + rg * 4;
                #pragma unroll
                for (int u = 0; u < 4; u++)
                    buf[base + u][j] = acc[s4 * 4 + u];
            }
            __syncthreads();

            if (donorm) {
                float ss = 0.f;
                #pragma unroll
                for (int t = 0; t < 16; t++) {
                    float v = buf[rg * 16 + t][j];
                    ss += v * v;
                }
                part[rg][j] = ss;
                __syncthreads();
                if (tid < 64) {
                    float s = part[0][tid] + part[1][tid] + part[2][tid] + part[3][tid];
                    scl[tid] = 1.0f / fmaxf(sqrtf(s), 1e-6f);
                }
                __syncthreads();
            }

            // transpose-store fp16: [l][dk], dk contiguous
            if (rows == 64) {
                for (int idx = tid; idx < 64 * 64; idx += 256) {
                    int l = idx >> 6, d = idx & 63;
                    float v = buf[d][l];
                    if (donorm) v *= scl[l];
                    outh[(size_t)(l0 + l) * 64 + d] = __float2half_rn(v);
                }
            } else {
                for (int idx = tid; idx < 64 * 32; idx += 256) {
                    int l = idx >> 5, d = idx & 31;
                    outh[(size_t)(l0 + l) * 32 + d] = __float2half_rn(buf[d][l]);
                }
            }
        }
    }
}

// ---------------------------------------------------------------------------
// Kernel C: HMMA flash attention (no online max: cosine logits in [-1,1]).
// BM=128 queries/block, BN=64 keys/iter. 8 warps; warp w owns rows 16w..16w+15.
// grid (32, NH), block 256.
// ---------------------------------------------------------------------------
#define BM 128
#define BN 64
#define QP 72   // smem pitch (halves): 144B rows -> conflict-free ldmatrix
#define KP 72
#define VPH 40  // 80B rows -> conflict-free ldmatrix

__global__ __launch_bounds__(256) void attn_kernel()
{
    extern __shared__ __align__(16) char smraw[];
    __half* Qs = (__half*)smraw;            // [128][QP]
    __half* Ks = Qs + BM * QP;              // [64][KP]
    __half* Vs = Ks + BN * KP;              // [64][VPH]
    float*  Zs = (float*)(Vs + BN * VPH);   // [128]

    const int nh = blockIdx.y;
    const int q0 = blockIdx.x * BM;
    const int tid = threadIdx.x;
    const int warp = tid >> 5, lane = tid & 31;

    const __half* Qp = Qh + (size_t)nh * LL * DKK;
    const __half* Kp = Kh + (size_t)nh * LL * DKK;
    const __half* Vp = Vh + (size_t)nh * LL * DVV;

    // load Q tile (128 x 64 halves), 8 halves per uint4
    #pragma unroll
    for (int t = 0; t < 4; t++) {
        int idx = tid + 256 * t;
        int row = idx >> 3, c8 = idx & 7;
        *(uint4*)&Qs[row * QP + c8 * 8] = *(const uint4*)&Qp[(size_t)(q0 + row) * 64 + c8 * 8];
    }
    if (tid < BM) Zs[tid] = 0.f;
    __syncthreads();

    // loop-invariant A fragments for S = Q K^T (warp rows 16w..16w+15)
    uint32_t aq[4][4];
    {
        const int m = lane >> 3, rw = lane & 7;
        #pragma unroll
        for (int kc = 0; kc < 4; kc++) {
            int row = warp * 16 + (m & 1) * 8 + rw;
            int col = kc * 16 + (m >> 1) * 8;
            uint32_t addr = (uint32_t)__cvta_generic_to_shared(&Qs[row * QP + col]);
            ldsm4(aq[kc][0], aq[kc][1], aq[kc][2], aq[kc][3], addr);
        }
    }

    float oacc[4][4] = {};  // [dv_block][frag] : warp-level 16x32 output

    for (int kt = 0; kt < LL / BN; kt++) {
        const int k0 = kt * BN;
        __syncthreads();
        #pragma unroll
        for (int t = 0; t < 2; t++) {
            int idx = tid + 256 * t;
            int row = idx >> 3, c8 = idx & 7;
            *(uint4*)&Ks[row * KP + c8 * 8] = *(const uint4*)&Kp[(size_t)(k0 + row) * 64 + c8 * 8];
        }
        {
            int row = tid >> 2, c8 = tid & 3;
            *(uint4*)&Vs[row * VPH + c8 * 8] = *(const uint4*)&Vp[(size_t)(k0 + row) * 32 + c8 * 8];
        }
        __syncthreads();

        // ---- S = Q K^T : warp computes 16x64, accum fp32 ----
        float sacc[8][4] = {};
        {
            const int m = lane >> 3, rw = lane & 7;
            #pragma unroll
            for (int kc = 0; kc < 4; kc++) {
                #pragma unroll
                for (int p = 0; p < 4; p++) {   // pair of 8-wide n-blocks
                    int row = p * 16 + (m >> 1) * 8 + rw;   // key index
                    int col = kc * 16 + (m & 1) * 8;        // dk index
                    uint32_t b0, b1, b2, b3;
                    uint32_t addr = (uint32_t)__cvta_generic_to_shared(&Ks[row * KP + col]);
                    ldsm4(b0, b1, b2, b3, addr);
                    mma16816(sacc[2 * p],     aq[kc], b0, b1);
                    mma16816(sacc[2 * p + 1], aq[kc], b2, b3);
                }
            }
        }

        // ---- P = exp(S); accumulate row sums ----
        float rlo = 0.f, rhi = 0.f;
        #pragma unroll
        for (int nb = 0; nb < 8; nb++) {
            #pragma unroll
            for (int e = 0; e < 4; e++) sacc[nb][e] = __expf(sacc[nb][e]);
            rlo += sacc[nb][0] + sacc[nb][1];
            rhi += sacc[nb][2] + sacc[nb][3];
        }
        rlo += __shfl_xor_sync(0xffffffffu, rlo, 1);
        rlo += __shfl_xor_sync(0xffffffffu, rlo, 2);
        rhi += __shfl_xor_sync(0xffffffffu, rhi, 1);
        rhi += __shfl_xor_sync(0xffffffffu, rhi, 2);
        if ((lane & 3) == 0) {
            Zs[warp * 16 + (lane >> 2)]     += rlo;
            Zs[warp * 16 + 8 + (lane >> 2)] += rhi;
        }

        // ---- pack P into A fragments (C->A identity for m16n8k16) ----
        uint32_t ap[4][4];
        #pragma unroll
        for (int t = 0; t < 4; t++) {
            ap[t][0] = pack_h2(sacc[2 * t][0],     sacc[2 * t][1]);
            ap[t][1] = pack_h2(sacc[2 * t][2],     sacc[2 * t][3]);
            ap[t][2] = pack_h2(sacc[2 * t + 1][0], sacc[2 * t + 1][1]);
            ap[t][3] = pack_h2(sacc[2 * t + 1][2], sacc[2 * t + 1][3]);
        }

        // ---- O += P V ----
        {
            const int m = lane >> 3, rw = lane & 7;
            #pragma unroll
            for (int t = 0; t < 4; t++) {        // k-chunk over keys
                #pragma unroll
                for (int vb = 0; vb < 2; vb++) { // pair of dv-blocks
                    int row = t * 16 + (m & 1) * 8 + rw;   // key
                    int col = vb * 16 + (m >> 1) * 8;      // dv
                    uint32_t b0, b1, b2, b3;
                    uint32_t addr = (uint32_t)__cvta_generic_to_shared(&Vs[row * VPH + col]);
                    ldsm4t(b0, b1, b2, b3, addr);
                    mma16816(oacc[2 * vb],     ap[t], b0, b1);
                    mma16816(oacc[2 * vb + 1], ap[t], b2, b3);
                }
            }
        }
    }
    __syncthreads();

    // ---- normalize + store ----
    const int n = nh >> 1, h = nh & 1;
    const int r = lane >> 2, q = lane & 3;
    const int row0 = warp * 16 + r;
    const float inv0 = 1.0f / Zs[row0];
    const float inv1 = 1.0f / Zs[row0 + 8];
    #pragma unroll
    for (int vb = 0; vb < 4; vb++) {
        int dv = vb * 8 + 2 * q;
        int l0v = q0 + row0;
        *(float2*)&Rg[((size_t)n * LL + l0v) * 64 + h * 32 + dv] =
            make_float2(oacc[vb][0] * inv0, oacc[vb][1] * inv0);
        *(float2*)&Rg[((size_t)n * LL + l0v + 8) * 64 + h * 32 + dv] =
            make_float2(oacc[vb][2] * inv1, oacc[vb][3] * inv1);
    }
}

// ---------------------------------------------------------------------------
// Kernel D: output projection + bias + residual. grid (64, NB), block 256.
// ---------------------------------------------------------------------------
__global__ __launch_bounds__(256) void out_kernel(
    const float* __restrict__ x,
    const float* __restrict__ Wm, const float* __restrict__ bm,
    float* __restrict__ out)
{
    __shared__ float Rst[64][65];
    __shared__ float wm[64][64];
    const int lt = blockIdx.x, n = blockIdx.y;
    const int l0 = lt * 64;
    const int tid = threadIdx.x;
    const int j = tid & 63, rg = tid >> 6;

    #pragma unroll
    for (int t = 0; t < 16; t++) {
        int i = rg + 4 * t;
        Rst[j][i] = Rg[((size_t)n * LL + l0 + i) * 64 + j];
    }
    #pragma unroll
    for (int t = 0; t < 16; t++) {
        int c = rg + 4 * t;
        wm[c][j] = Wm[c * 64 + j];
    }
    __syncthreads();

    #pragma unroll
    for (int s4 = 0; s4 < 4; s4++) {
        const int base = s4 * 16 + rg * 4;
        float accs[4];
        #pragma unroll
        for (int u = 0; u < 4; u++) accs[u] = bm[base + u];
        #pragma unroll
        for (int jj = 0; jj < 64; jj++) {
            float rv = Rst[jj][j];
            #pragma unroll
            for (int u = 0; u < 4; u++) accs[u] += wm[base + u][jj] * rv;
        }
        #pragma unroll
        for (int u = 0; u < 4; u++) {
            int c = base + u;
            size_t idx = ((size_t)(n * CCH + c)) * LL + l0 + j;
            out[idx] = accs[u] + x[idx];
        }
    }
}

// ---------------------------------------------------------------------------
extern "C" void kernel_launch(void* const* d_in, const int* in_sizes, int n_in,
                              void* d_out, int out_size)
{
    const float* x  = (const float*)d_in[0];
    const float* Wq = (const float*)d_in[1];
    const float* bq = (const float*)d_in[2];
    const float* Wk = (const float*)d_in[3];
    const float* bk = (const float*)d_in[4];
    const float* Wv = (const float*)d_in[5];
    const float* bv = (const float*)d_in[6];
    const float* Wm = (const float*)d_in[7];
    const float* bm = (const float*)d_in[8];
    float* out = (float*)d_out;

    qkvn_kernel<<<dim3(64, NB), 256>>>(x, Wq, bq, Wk, bk, Wv, bv);

    const size_t smB = (size_t)(BM * QP + BN * KP + BN * VPH) * sizeof(__half) + BM * sizeof(float);
    attn_kernel<<<dim3(LL / BM, NHH), 256, smB>>>();

    out_kernel<<<dim3(64, NB), 256>>>(x, Wm, bm, out);
}

// round 5
// speedup vs baseline: 4.9840x; 1.1004x over previous
#include <cuda_runtime.h>
#include <cuda_fp16.h>
#include <cstdint>

// Fixed problem shape
#define NB    2
#define CCH   64
#define LL    4096
#define HEADS 2
#define DKK   64
#define DVV   32
#define NHH   4

// fp16 activations, l-major: [nh][L][dk]. Q is pre-scaled by log2(e).
__device__ __half Qh[NHH * LL * DKK];
__device__ __half Kh[NHH * LL * DKK];
__device__ __half Vh[NHH * LL * DVV];
__device__ float  Rg[NB * LL * (HEADS * DVV)];   // [n][l][h*DV+v]

// ---------------------------------------------------------------------------
// PTX helpers
// ---------------------------------------------------------------------------
__device__ __forceinline__ void ldsm4(uint32_t& r0, uint32_t& r1, uint32_t& r2, uint32_t& r3, uint32_t a) {
    asm volatile("ldmatrix.sync.aligned.m8n8.x4.shared.b16 {%0,%1,%2,%3}, [%4];\n"
                 : "=r"(r0), "=r"(r1), "=r"(r2), "=r"(r3) : "r"(a));
}
__device__ __forceinline__ void ldsm4t(uint32_t& r0, uint32_t& r1, uint32_t& r2, uint32_t& r3, uint32_t a) {
    asm volatile("ldmatrix.sync.aligned.m8n8.x4.trans.shared.b16 {%0,%1,%2,%3}, [%4];\n"
                 : "=r"(r0), "=r"(r1), "=r"(r2), "=r"(r3) : "r"(a));
}
__device__ __forceinline__ void mma16816(float* c, const uint32_t* a, uint32_t b0, uint32_t b1) {
    asm volatile("mma.sync.aligned.m16n8k16.row.col.f32.f16.f16.f32 "
                 "{%0,%1,%2,%3}, {%4,%5,%6,%7}, {%8,%9}, {%0,%1,%2,%3};\n"
                 : "+f"(c[0]), "+f"(c[1]), "+f"(c[2]), "+f"(c[3])
                 : "r"(a[0]), "r"(a[1]), "r"(a[2]), "r"(a[3]), "r"(b0), "r"(b1));
}
// pack two floats to half2 and take 2^x of both halves in one MUFU op
__device__ __forceinline__ uint32_t ex2h2(float x, float y) {
    __half2 h = __floats2half2_rn(x, y);
    uint32_t in = *(uint32_t*)&h, r;
    asm("ex2.approx.f16x2 %0, %1;\n" : "=r"(r) : "r"(in));
    return r;
}

// ---------------------------------------------------------------------------
// Kernel A: QKV projection + bias + (Q,K) L2-normalize + fp16 transpose-store.
// One (head, section) per block-z. Q additionally scaled by log2(e).
// grid (64, NB, 6), block 256.
// ---------------------------------------------------------------------------
__global__ __launch_bounds__(256) void qkvn_kernel(
    const float* __restrict__ x,
    const float* __restrict__ Wq, const float* __restrict__ bq,
    const float* __restrict__ Wk, const float* __restrict__ bk,
    const float* __restrict__ Wv, const float* __restrict__ bv)
{
    __shared__ float xs[64][64];     // [c][l_local]
    __shared__ float ws[64][65];     // weights [row][c], then staging [row][l]
    __shared__ float part[4][64];
    __shared__ float scl[64];
    const int lt = blockIdx.x, n = blockIdx.y, z = blockIdx.z;
    const int h = z / 3, sec = z % 3;
    const int nh = n * HEADS + h;
    const int l0 = lt * 64;
    const int tid = threadIdx.x;
    const int j = tid & 63, rg = tid >> 6;

    const float* W; const float* b; __half* outh; int rows; bool donorm; float extra;
    if (sec == 0)      { W = Wq + h * DKK * CCH; b = bq + h * DKK; outh = Qh + (size_t)nh * LL * DKK; rows = 64; donorm = true;  extra = 1.44269504f; }
    else if (sec == 1) { W = Wk + h * DKK * CCH; b = bk + h * DKK; outh = Kh + (size_t)nh * LL * DKK; rows = 64; donorm = true;  extra = 1.0f; }
    else               { W = Wv + h * DVV * CCH; b = bv + h * DVV; outh = Vh + (size_t)nh * LL * DVV; rows = 32; donorm = false; extra = 1.0f; }

    #pragma unroll
    for (int t = 0; t < 16; t++) {
        int c = rg + 4 * t;
        xs[c][j] = x[((size_t)(n * CCH + c)) * LL + l0 + j];
    }
    for (int idx = tid; idx < rows * 64; idx += 256)
        ws[idx >> 6][idx & 63] = W[idx];
    __syncthreads();

    // GEMM: thread computes rows {s4*16 + rg*4 + u} at column j
    float acc[16];
    const int nchunk = rows / 16;
    for (int s4 = 0; s4 < nchunk; s4++) {
        const int base = s4 * 16 + rg * 4;
        float a0 = b[base], a1 = b[base + 1], a2 = b[base + 2], a3 = b[base + 3];
        #pragma unroll
        for (int c = 0; c < 64; c++) {
            float xv = xs[c][j];
            a0 += ws[base + 0][c] * xv;
            a1 += ws[base + 1][c] * xv;
            a2 += ws[base + 2][c] * xv;
            a3 += ws[base + 3][c] * xv;
        }
        acc[s4 * 4 + 0] = a0; acc[s4 * 4 + 1] = a1;
        acc[s4 * 4 + 2] = a2; acc[s4 * 4 + 3] = a3;
    }
    __syncthreads();   // done reading weights; reuse ws as staging
    for (int s4 = 0; s4 < nchunk; s4++) {
        const int base = s4 * 16 + rg * 4;
        #pragma unroll
        for (int u = 0; u < 4; u++)
            ws[base + u][j] = acc[s4 * 4 + u];
    }
    __syncthreads();

    if (donorm) {
        float ss = 0.f;
        #pragma unroll
        for (int t = 0; t < 16; t++) {
            float v = ws[rg * 16 + t][j];
            ss += v * v;
        }
        part[rg][j] = ss;
        __syncthreads();
        if (tid < 64) {
            float s = part[0][tid] + part[1][tid] + part[2][tid] + part[3][tid];
            scl[tid] = extra / fmaxf(sqrtf(s), 1e-6f);
        }
        __syncthreads();
    }

    // transpose-store fp16: [l][dk], dk contiguous
    if (rows == 64) {
        #pragma unroll
        for (int t = 0; t < 16; t++) {
            int idx = tid + 256 * t;
            int l = idx >> 6, d = idx & 63;
            float v = ws[d][l];
            if (donorm) v *= scl[l];
            outh[(size_t)(l0 + l) * 64 + d] = __float2half_rn(v);
        }
    } else {
        #pragma unroll
        for (int t = 0; t < 8; t++) {
            int idx = tid + 256 * t;
            int l = idx >> 5, d = idx & 31;
            outh[(size_t)(l0 + l) * 32 + d] = __float2half_rn(ws[d][l]);
        }
    }
}

// ---------------------------------------------------------------------------
// Kernel C: HMMA flash attention. Cosine logits bounded -> no online max.
// Q pre-scaled by log2e, so P = ex2(S) directly (ex2.approx.f16x2, 2/MUFU op).
// Row sums Z computed by an extra mma against an all-ones B fragment.
// grid (32, NH), block 256.
// ---------------------------------------------------------------------------
#define BM 128
#define BN 64
#define QP 72   // smem pitch (halves): conflict-free ldmatrix
#define KP 72
#define VPH 40

#define ONES_H2 0x3C003C00u

__global__ __launch_bounds__(256) void attn_kernel()
{
    extern __shared__ __align__(16) char smraw[];
    __half* Qs = (__half*)smraw;            // [128][QP]
    __half* Ks = Qs + BM * QP;              // [64][KP]
    __half* Vs = Ks + BN * KP;              // [64][VPH]

    const int nh = blockIdx.y;
    const int q0 = blockIdx.x * BM;
    const int tid = threadIdx.x;
    const int warp = tid >> 5, lane = tid & 31;

    const __half* Qp = Qh + (size_t)nh * LL * DKK;
    const __half* Kp = Kh + (size_t)nh * LL * DKK;
    const __half* Vp = Vh + (size_t)nh * LL * DVV;

    // load Q tile (128 x 64 halves)
    #pragma unroll
    for (int t = 0; t < 4; t++) {
        int idx = tid + 256 * t;
        int row = idx >> 3, c8 = idx & 7;
        *(uint4*)&Qs[row * QP + c8 * 8] = *(const uint4*)&Qp[(size_t)(q0 + row) * 64 + c8 * 8];
    }
    __syncthreads();

    // loop-invariant A fragments for S = Q K^T (warp rows 16w..16w+15)
    uint32_t aq[4][4];
    {
        const int m = lane >> 3, rw = lane & 7;
        #pragma unroll
        for (int kc = 0; kc < 4; kc++) {
            int row = warp * 16 + (m & 1) * 8 + rw;
            int col = kc * 16 + (m >> 1) * 8;
            uint32_t addr = (uint32_t)__cvta_generic_to_shared(&Qs[row * QP + col]);
            ldsm4(aq[kc][0], aq[kc][1], aq[kc][2], aq[kc][3], addr);
        }
    }

    float oacc[4][4] = {};  // [dv_block][frag] : warp-level 16x32 output
    float zacc[4] = {};     // row sums via ones-mma

    for (int kt = 0; kt < LL / BN; kt++) {
        const int k0 = kt * BN;
        __syncthreads();
        #pragma unroll
        for (int t = 0; t < 2; t++) {
            int idx = tid + 256 * t;
            int row = idx >> 3, c8 = idx & 7;
            *(uint4*)&Ks[row * KP + c8 * 8] = *(const uint4*)&Kp[(size_t)(k0 + row) * 64 + c8 * 8];
        }
        {
            int row = tid >> 2, c8 = tid & 3;
            *(uint4*)&Vs[row * VPH + c8 * 8] = *(const uint4*)&Vp[(size_t)(k0 + row) * 32 + c8 * 8];
        }
        __syncthreads();

        // ---- S = Q K^T (pre-scaled by log2e) : warp computes 16x64 ----
        float sacc[8][4] = {};
        {
            const int m = lane >> 3, rw = lane & 7;
            #pragma unroll
            for (int kc = 0; kc < 4; kc++) {
                #pragma unroll
                for (int p = 0; p < 4; p++) {
                    int row = p * 16 + (m >> 1) * 8 + rw;   // key index
                    int col = kc * 16 + (m & 1) * 8;        // dk index
                    uint32_t b0, b1, b2, b3;
                    uint32_t addr = (uint32_t)__cvta_generic_to_shared(&Ks[row * KP + col]);
                    ldsm4(b0, b1, b2, b3, addr);
                    mma16816(sacc[2 * p],     aq[kc], b0, b1);
                    mma16816(sacc[2 * p + 1], aq[kc], b2, b3);
                }
            }
        }

        // ---- P = 2^S in fp16, packed directly as A fragments ----
        uint32_t ap[4][4];
        #pragma unroll
        for (int t = 0; t < 4; t++) {
            ap[t][0] = ex2h2(sacc[2 * t][0],     sacc[2 * t][1]);
            ap[t][1] = ex2h2(sacc[2 * t][2],     sacc[2 * t][3]);
            ap[t][2] = ex2h2(sacc[2 * t + 1][0], sacc[2 * t + 1][1]);
            ap[t][3] = ex2h2(sacc[2 * t + 1][2], sacc[2 * t + 1][3]);
        }

        // ---- O += P V ; Z += P * ones ----
        {
            const int m = lane >> 3, rw = lane & 7;
            #pragma unroll
            for (int t = 0; t < 4; t++) {        // k-chunk over keys
                #pragma unroll
                for (int vb = 0; vb < 2; vb++) { // pair of dv-blocks
                    int row = t * 16 + (m & 1) * 8 + rw;   // key
                    int col = vb * 16 + (m >> 1) * 8;      // dv
                    uint32_t b0, b1, b2, b3;
                    uint32_t addr = (uint32_t)__cvta_generic_to_shared(&Vs[row * VPH + col]);
                    ldsm4t(b0, b1, b2, b3, addr);
                    mma16816(oacc[2 * vb],     ap[t], b0, b1);
                    mma16816(oacc[2 * vb + 1], ap[t], b2, b3);
                }
                mma16816(zacc, ap[t], ONES_H2, ONES_H2);
            }
        }
    }

    // ---- normalize + store: zacc[0]=Z(row), zacc[2]=Z(row+8) ----
    const int n = nh >> 1, h = nh & 1;
    const int r = lane >> 2, q = lane & 3;
    const int row0 = warp * 16 + r;
    const float inv0 = 1.0f / zacc[0];
    const float inv1 = 1.0f / zacc[2];
    #pragma unroll
    for (int vb = 0; vb < 4; vb++) {
        int dv = vb * 8 + 2 * q;
        int l0v = q0 + row0;
        *(float2*)&Rg[((size_t)n * LL + l0v) * 64 + h * 32 + dv] =
            make_float2(oacc[vb][0] * inv0, oacc[vb][1] * inv0);
        *(float2*)&Rg[((size_t)n * LL + l0v + 8) * 64 + h * 32 + dv] =
            make_float2(oacc[vb][2] * inv1, oacc[vb][3] * inv1);
    }
}

// ---------------------------------------------------------------------------
// Kernel D: output projection + bias + residual. 32-wide l tiles.
// grid (128, NB), block 256. Thread computes 8 channels x 1 column.
// ---------------------------------------------------------------------------
__global__ __launch_bounds__(256) void out_kernel(
    const float* __restrict__ x,
    const float* __restrict__ Wm, const float* __restrict__ bm,
    float* __restrict__ out)
{
    __shared__ float Rst[64][33];   // [d][l_local]
    __shared__ float wm[64][64];    // [o][c]
    const int lt = blockIdx.x, n = blockIdx.y;
    const int l0 = lt * 32;
    const int tid = threadIdx.x;
    const int j = tid & 31, rg = tid >> 5;

    #pragma unroll
    for (int t = 0; t < 8; t++) {
        int idx = tid + 256 * t;
        int l = idx >> 6, d = idx & 63;
        Rst[d][l] = Rg[((size_t)n * LL + l0 + l) * 64 + d];
    }
    #pragma unroll
    for (int t = 0; t < 16; t++) {
        int idx = tid + 256 * t;
        wm[idx >> 6][idx & 63] = Wm[idx];
    }
    __syncthreads();

    float accs[8];
    #pragma unroll
    for (int u = 0; u < 8; u++) accs[u] = bm[rg * 8 + u];
    #pragma unroll
    for (int d = 0; d < 64; d++) {
        float rv = Rst[d][j];
        #pragma unroll
        for (int u = 0; u < 8; u++) accs[u] += wm[rg * 8 + u][d] * rv;
    }
    #pragma unroll
    for (int u = 0; u < 8; u++) {
        int c = rg * 8 + u;
        size_t idx = ((size_t)(n * CCH + c)) * LL + l0 + j;
        out[idx] = accs[u] + x[idx];
    }
}

// ---------------------------------------------------------------------------
extern "C" void kernel_launch(void* const* d_in, const int* in_sizes, int n_in,
                              void* d_out, int out_size)
{
    const float* x  = (const float*)d_in[0];
    const float* Wq = (const float*)d_in[1];
    const float* bq = (const float*)d_in[2];
    const float* Wk = (const float*)d_in[3];
    const float* bk = (const float*)d_in[4];
    const float* Wv = (const float*)d_in[5];
    const float* bv = (const float*)d_in[6];
    const float* Wm = (const float*)d_in[7];
    const float* bm = (const float*)d_in[8];
    float* out = (float*)d_out;

    qkvn_kernel<<<dim3(64, NB, 6), 256>>>(x, Wq, bq, Wk, bk, Wv, bv);

    const size_t smB = (size_t)(BM * QP + BN * KP + BN * VPH) * sizeof(__half);
    attn_kernel<<<dim3(LL / BM, NHH), 256, smB>>>();

    out_kernel<<<dim3(128, NB), 256>>>(x, Wm, bm, out);
}

// round 7
// speedup vs baseline: 6.7226x; 1.3488x over previous
#include <cuda_runtime.h>
#include <cuda_fp16.h>
#include <cstdint>

// Fixed problem shape
#define NB    2
#define CCH   64
#define LL    4096
#define HEADS 2
#define DKK   64
#define DVV   32
#define NHH   4
#define NSPLIT 2
#define KT_PER_SPLIT (LL / 64 / NSPLIT)   // 32

// fp16 activations, l-major: [nh][L][dk]. Q is pre-scaled by log2(e).
__device__ __half Qh[NHH * LL * DKK];
__device__ __half Kh[NHH * LL * DKK];
__device__ __half Vh[NHH * LL * DVV];
__device__ float  Og[NSPLIT * NB * LL * (HEADS * DVV)];  // unnormalized partials
__device__ float  Zg[NSPLIT * NHH * LL];                 // partial row sums

// ---------------------------------------------------------------------------
// PTX helpers
// ---------------------------------------------------------------------------
__device__ __forceinline__ void ldsm4(uint32_t& r0, uint32_t& r1, uint32_t& r2, uint32_t& r3, uint32_t a) {
    asm volatile("ldmatrix.sync.aligned.m8n8.x4.shared.b16 {%0,%1,%2,%3}, [%4];\n"
                 : "=r"(r0), "=r"(r1), "=r"(r2), "=r"(r3) : "r"(a));
}
__device__ __forceinline__ void ldsm4t(uint32_t& r0, uint32_t& r1, uint32_t& r2, uint32_t& r3, uint32_t a) {
    asm volatile("ldmatrix.sync.aligned.m8n8.x4.trans.shared.b16 {%0,%1,%2,%3}, [%4];\n"
                 : "=r"(r0), "=r"(r1), "=r"(r2), "=r"(r3) : "r"(a));
}
__device__ __forceinline__ void mma16816(float* c, const uint32_t* a, uint32_t b0, uint32_t b1) {
    asm volatile("mma.sync.aligned.m16n8k16.row.col.f32.f16.f16.f32 "
                 "{%0,%1,%2,%3}, {%4,%5,%6,%7}, {%8,%9}, {%0,%1,%2,%3};\n"
                 : "+f"(c[0]), "+f"(c[1]), "+f"(c[2]), "+f"(c[3])
                 : "r"(a[0]), "r"(a[1]), "r"(a[2]), "r"(a[3]), "r"(b0), "r"(b1));
}
__device__ __forceinline__ uint32_t ex2h2(float x, float y) {
    __half2 h = __floats2half2_rn(x, y);
    uint32_t in = *(uint32_t*)&h, r;
    asm("ex2.approx.f16x2 %0, %1;\n" : "=r"(r) : "r"(in));
    return r;
}

// ---------------------------------------------------------------------------
// Kernel A: QKV projection + bias + (Q,K) L2-normalize + fp16 transpose-store.
// 16x16 thread grid, 4x4 (or 2x4) outputs/thread, float4 smem operand reads.
// grid (64, NB, 6), block 256.
// ---------------------------------------------------------------------------
#define WSP 68   // transposed weight pitch (floats), float4-aligned
#define STP 65   // staging pitch: conflict-free transposed reads

__global__ __launch_bounds__(256) void qkvn_kernel(
    const float* __restrict__ x,
    const float* __restrict__ Wq, const float* __restrict__ bq,
    const float* __restrict__ Wk, const float* __restrict__ bk,
    const float* __restrict__ Wv, const float* __restrict__ bv)
{
    __shared__ __align__(16) float xs[64][64];    // [c][l_local]
    __shared__ __align__(16) float wst[64 * WSP]; // weights [c][row]; reused as staging [row][l] pitch STP
    __shared__ float part[4][64];
    __shared__ float scl[64];
    const int lt = blockIdx.x, n = blockIdx.y, z = blockIdx.z;
    const int h = z / 3, sec = z % 3;
    const int nh = n * HEADS + h;
    const int l0 = lt * 64;
    const int tid = threadIdx.x;
    const int ty = tid >> 4, tx = tid & 15;
    const int j = tid & 63, rg = tid >> 6;

    const float* W; const float* b; __half* outh; int rows; bool donorm; float extra;
    if (sec == 0)      { W = Wq + h * DKK * CCH; b = bq + h * DKK; outh = Qh + (size_t)nh * LL * DKK; rows = 64; donorm = true;  extra = 1.44269504f; }
    else if (sec == 1) { W = Wk + h * DKK * CCH; b = bk + h * DKK; outh = Kh + (size_t)nh * LL * DKK; rows = 64; donorm = true;  extra = 1.0f; }
    else               { W = Wv + h * DVV * CCH; b = bv + h * DVV; outh = Vh + (size_t)nh * LL * DVV; rows = 32; donorm = false; extra = 1.0f; }

    #pragma unroll
    for (int t = 0; t < 16; t++) {
        int c = rg + 4 * t;
        xs[c][j] = x[((size_t)(n * CCH + c)) * LL + l0 + j];
    }
    // weights transposed: wst[c][row]
    for (int idx = tid; idx < rows * 64; idx += 256) {
        int r = idx >> 6, c = idx & 63;
        wst[c * WSP + r] = W[idx];
    }
    __syncthreads();

    if (rows == 64) {
        // thread: rows ty*4..+3, cols (l) tx*4..+3
        float acc[4][4];
        #pragma unroll
        for (int u = 0; u < 4; u++) {
            float bb = b[ty * 4 + u];
            #pragma unroll
            for (int v = 0; v < 4; v++) acc[u][v] = bb;
        }
        #pragma unroll 8
        for (int c = 0; c < 64; c++) {
            float4 wv = *(const float4*)&wst[c * WSP + ty * 4];
            float4 xv = *(const float4*)&xs[c][tx * 4];
            float wa[4] = {wv.x, wv.y, wv.z, wv.w};
            float xa[4] = {xv.x, xv.y, xv.z, xv.w};
            #pragma unroll
            for (int u = 0; u < 4; u++) {
                #pragma unroll
                for (int v = 0; v < 4; v++)
                    acc[u][v] += wa[u] * xa[v];
            }
        }
        __syncthreads();   // finish reading weights before staging overwrite
        #pragma unroll
        for (int u = 0; u < 4; u++) {
            #pragma unroll
            for (int v = 0; v < 4; v++)
                wst[(ty * 4 + u) * STP + tx * 4 + v] = acc[u][v];
        }
        __syncthreads();

        if (donorm) {
            float ss = 0.f;
            #pragma unroll
            for (int t = 0; t < 16; t++) {
                float v = wst[(rg * 16 + t) * STP + j];
                ss += v * v;
            }
            part[rg][j] = ss;
            __syncthreads();
            if (tid < 64) {
                float s = part[0][tid] + part[1][tid] + part[2][tid] + part[3][tid];
                scl[tid] = extra / fmaxf(sqrtf(s), 1e-6f);
            }
            __syncthreads();
        }
        #pragma unroll
        for (int t = 0; t < 16; t++) {
            int idx = tid + 256 * t;
            int l = idx >> 6, d = idx & 63;
            float v = wst[d * STP + l];
            if (donorm) v *= scl[l];
            outh[(size_t)(l0 + l) * 64 + d] = __float2half_rn(v);
        }
    } else {
        // V: rows=32. thread: rows ty*2..+1, cols tx*4..+3
        float acc[2][4];
        #pragma unroll
        for (int u = 0; u < 2; u++) {
            float bb = b[ty * 2 + u];
            #pragma unroll
            for (int v = 0; v < 4; v++) acc[u][v] = bb;
        }
        #pragma unroll 8
        for (int c = 0; c < 64; c++) {
            float2 wv = *(const float2*)&wst[c * WSP + ty * 2];
            float4 xv = *(const float4*)&xs[c][tx * 4];
            float wa[2] = {wv.x, wv.y};
            float xa[4] = {xv.x, xv.y, xv.z, xv.w};
            #pragma unroll
            for (int u = 0; u < 2; u++) {
                #pragma unroll
                for (int v = 0; v < 4; v++)
                    acc[u][v] += wa[u] * xa[v];
            }
        }
        __syncthreads();
        #pragma unroll
        for (int u = 0; u < 2; u++) {
            #pragma unroll
            for (int v = 0; v < 4; v++)
                wst[(ty * 2 + u) * STP + tx * 4 + v] = acc[u][v];
        }
        __syncthreads();
        #pragma unroll
        for (int t = 0; t < 8; t++) {
            int idx = tid + 256 * t;
            int l = idx >> 5, d = idx & 31;
            outh[(size_t)(l0 + l) * 32 + d] = __float2half_rn(wst[d * STP + l]);
        }
    }
}

// ---------------------------------------------------------------------------
// Kernel C: HMMA flash attention, split-K over 2 halves of the key range.
// Writes unnormalized O partials + Z partials. grid (32, NH, 2), block 256.
// ---------------------------------------------------------------------------
#define BM 128
#define BN 64
#define QP 72
#define KP 72
#define VPH 40
#define ONES_H2 0x3C003C00u

__global__ __launch_bounds__(256, 2) void attn_kernel()
{
    extern __shared__ __align__(16) char smraw[];
    __half* Qs = (__half*)smraw;            // [128][QP]
    __half* Ks = Qs + BM * QP;              // [64][KP]
    __half* Vs = Ks + BN * KP;              // [64][VPH]

    const int nh = blockIdx.y;
    const int q0 = blockIdx.x * BM;
    const int split = blockIdx.z;
    const int tid = threadIdx.x;
    const int warp = tid >> 5, lane = tid & 31;

    const __half* Qp = Qh + (size_t)nh * LL * DKK;
    const __half* Kp = Kh + (size_t)nh * LL * DKK;
    const __half* Vp = Vh + (size_t)nh * LL * DVV;

    #pragma unroll
    for (int t = 0; t < 4; t++) {
        int idx = tid + 256 * t;
        int row = idx >> 3, c8 = idx & 7;
        *(uint4*)&Qs[row * QP + c8 * 8] = *(const uint4*)&Qp[(size_t)(q0 + row) * 64 + c8 * 8];
    }
    __syncthreads();

    uint32_t aq[4][4];
    {
        const int m = lane >> 3, rw = lane & 7;
        #pragma unroll
        for (int kc = 0; kc < 4; kc++) {
            int row = warp * 16 + (m & 1) * 8 + rw;
            int col = kc * 16 + (m >> 1) * 8;
            uint32_t addr = (uint32_t)__cvta_generic_to_shared(&Qs[row * QP + col]);
            ldsm4(aq[kc][0], aq[kc][1], aq[kc][2], aq[kc][3], addr);
        }
    }

    float oacc[4][4] = {};
    float zacc[4] = {};

    for (int kt = split * KT_PER_SPLIT; kt < (split + 1) * KT_PER_SPLIT; kt++) {
        const int k0 = kt * BN;
        __syncthreads();
        #pragma unroll
        for (int t = 0; t < 2; t++) {
            int idx = tid + 256 * t;
            int row = idx >> 3, c8 = idx & 7;
            *(uint4*)&Ks[row * KP + c8 * 8] = *(const uint4*)&Kp[(size_t)(k0 + row) * 64 + c8 * 8];
        }
        {
            int row = tid >> 2, c8 = tid & 3;
            *(uint4*)&Vs[row * VPH + c8 * 8] = *(const uint4*)&Vp[(size_t)(k0 + row) * 32 + c8 * 8];
        }
        __syncthreads();

        float sacc[8][4] = {};
        {
            const int m = lane >> 3, rw = lane & 7;
            #pragma unroll
            for (int kc = 0; kc < 4; kc++) {
                #pragma unroll
                for (int p = 0; p < 4; p++) {
                    int row = p * 16 + (m >> 1) * 8 + rw;
                    int col = kc * 16 + (m & 1) * 8;
                    uint32_t b0, b1, b2, b3;
                    uint32_t addr = (uint32_t)__cvta_generic_to_shared(&Ks[row * KP + col]);
                    ldsm4(b0, b1, b2, b3, addr);
                    mma16816(sacc[2 * p],     aq[kc], b0, b1);
                    mma16816(sacc[2 * p + 1], aq[kc], b2, b3);
                }
            }
        }

        uint32_t ap[4][4];
        #pragma unroll
        for (int t = 0; t < 4; t++) {
            ap[t][0] = ex2h2(sacc[2 * t][0],     sacc[2 * t][1]);
            ap[t][1] = ex2h2(sacc[2 * t][2],     sacc[2 * t][3]);
            ap[t][2] = ex2h2(sacc[2 * t + 1][0], sacc[2 * t + 1][1]);
            ap[t][3] = ex2h2(sacc[2 * t + 1][2], sacc[2 * t + 1][3]);
        }

        {
            const int m = lane >> 3, rw = lane & 7;
            #pragma unroll
            for (int t = 0; t < 4; t++) {
                #pragma unroll
                for (int vb = 0; vb < 2; vb++) {
                    int row = t * 16 + (m & 1) * 8 + rw;
                    int col = vb * 16 + (m >> 1) * 8;
                    uint32_t b0, b1, b2, b3;
                    uint32_t addr = (uint32_t)__cvta_generic_to_shared(&Vs[row * VPH + col]);
                    ldsm4t(b0, b1, b2, b3, addr);
                    mma16816(oacc[2 * vb],     ap[t], b0, b1);
                    mma16816(oacc[2 * vb + 1], ap[t], b2, b3);
                }
                mma16816(zacc, ap[t], ONES_H2, ONES_H2);
            }
        }
    }

    // ---- store unnormalized partials ----
    const int n = nh >> 1, h = nh & 1;
    const int r = lane >> 2, q = lane & 3;
    const int row0 = warp * 16 + r;
    if (q == 0) {
        Zg[((size_t)split * NHH + nh) * LL + q0 + row0]     = zacc[0];
        Zg[((size_t)split * NHH + nh) * LL + q0 + row0 + 8] = zacc[2];
    }
    #pragma unroll
    for (int vb = 0; vb < 4; vb++) {
        int dv = vb * 8 + 2 * q;
        int l0v = q0 + row0;
        *(float2*)&Og[((size_t)(split * NB + n) * LL + l0v) * 64 + h * 32 + dv] =
            make_float2(oacc[vb][0], oacc[vb][1]);
        *(float2*)&Og[((size_t)(split * NB + n) * LL + l0v + 8) * 64 + h * 32 + dv] =
            make_float2(oacc[vb][2], oacc[vb][3]);
    }
}

// ---------------------------------------------------------------------------
// Kernel D: split combine + output projection + bias + residual.
// grid (128, NB), block 256.
// ---------------------------------------------------------------------------
__global__ __launch_bounds__(256) void out_kernel(
    const float* __restrict__ x,
    const float* __restrict__ Wm, const float* __restrict__ bm,
    float* __restrict__ out)
{
    __shared__ float Rst[64][33];   // [d][l_local]
    __shared__ float wm[64][64];    // [o][c]
    __shared__ float zinv[2][32];
    const int lt = blockIdx.x, n = blockIdx.y;
    const int l0 = lt * 32;
    const int tid = threadIdx.x;
    const int j = tid & 31, rg = tid >> 5;

    if (tid < 64) {
        int h = tid >> 5, li = tid & 31;
        float z = Zg[((size_t)0 * NHH + n * HEADS + h) * LL + l0 + li]
                + Zg[((size_t)1 * NHH + n * HEADS + h) * LL + l0 + li];
        zinv[h][li] = 1.0f / z;
    }
    #pragma unroll
    for (int t = 0; t < 16; t++) {
        int idx = tid + 256 * t;
        wm[idx >> 6][idx & 63] = Wm[idx];
    }
    __syncthreads();

    #pragma unroll
    for (int t = 0; t < 8; t++) {
        int idx = tid + 256 * t;
        int l = idx >> 6, d = idx & 63;
        float o = Og[((size_t)(0 * NB + n) * LL + l0 + l) * 64 + d]
                + Og[((size_t)(1 * NB + n) * LL + l0 + l) * 64 + d];
        Rst[d][l] = o * zinv[d >> 5][l];
    }
    __syncthreads();

    float accs[8];
    #pragma unroll
    for (int u = 0; u < 8; u++) accs[u] = bm[rg * 8 + u];
    #pragma unroll
    for (int d = 0; d < 64; d++) {
        float rv = Rst[d][j];
        #pragma unroll
        for (int u = 0; u < 8; u++) accs[u] += wm[rg * 8 + u][d] * rv;
    }
    #pragma unroll
    for (int u = 0; u < 8; u++) {
        int c = rg * 8 + u;
        size_t idx = ((size_t)(n * CCH + c)) * LL + l0 + j;
        out[idx] = accs[u] + x[idx];
    }
}

// ---------------------------------------------------------------------------
extern "C" void kernel_launch(void* const* d_in, const int* in_sizes, int n_in,
                              void* d_out, int out_size)
{
    const float* x  = (const float*)d_in[0];
    const float* Wq = (const float*)d_in[1];
    const float* bq = (const float*)d_in[2];
    const float* Wk = (const float*)d_in[3];
    const float* bk = (const float*)d_in[4];
    const float* Wv = (const float*)d_in[5];
    const float* bv = (const float*)d_in[6];
    const float* Wm = (const float*)d_in[7];
    const float* bm = (const float*)d_in[8];
    float* out = (float*)d_out;

    qkvn_kernel<<<dim3(64, NB, 6), 256>>>(x, Wq, bq, Wk, bk, Wv, bv);

    const size_t smB = (size_t)(BM * QP + BN * KP + BN * VPH) * sizeof(__half);
    attn_kernel<<<dim3(LL / BM, NHH, NSPLIT), 256, smB>>>();

    out_kernel<<<dim3(128, NB), 256>>>(x, Wm, bm, out);
}

// round 9
// speedup vs baseline: 7.5179x; 1.1183x over previous
#include <cuda_runtime.h>
#include <cuda_fp16.h>
#include <cstdint>

// Fixed problem shape
#define NB    2
#define CCH   64
#define LL    4096
#define HEADS 2
#define DKK   64
#define DVV   32
#define NHH   4
#define NSPLIT 2
#define KT_PER_SPLIT (LL / 64 / NSPLIT)   // 32

// fp16 activations, l-major: [nh][L][dk]. Q is pre-scaled by log2(e).
__device__ __half Qh[NHH * LL * DKK];
__device__ __half Kh[NHH * LL * DKK];
__device__ __half Vh[NHH * LL * DVV];
__device__ float  Og[NSPLIT * NB * LL * (HEADS * DVV)];  // unnormalized partials
__device__ float  Zg[NSPLIT * NHH * LL];                 // partial row sums

// ---------------------------------------------------------------------------
// PTX helpers
// ---------------------------------------------------------------------------
__device__ __forceinline__ void ldsm4(uint32_t& r0, uint32_t& r1, uint32_t& r2, uint32_t& r3, uint32_t a) {
    asm volatile("ldmatrix.sync.aligned.m8n8.x4.shared.b16 {%0,%1,%2,%3}, [%4];\n"
                 : "=r"(r0), "=r"(r1), "=r"(r2), "=r"(r3) : "r"(a));
}
__device__ __forceinline__ void ldsm4t(uint32_t& r0, uint32_t& r1, uint32_t& r2, uint32_t& r3, uint32_t a) {
    asm volatile("ldmatrix.sync.aligned.m8n8.x4.trans.shared.b16 {%0,%1,%2,%3}, [%4];\n"
                 : "=r"(r0), "=r"(r1), "=r"(r2), "=r"(r3) : "r"(a));
}
__device__ __forceinline__ void mma16816(float* c, const uint32_t* a, uint32_t b0, uint32_t b1) {
    asm volatile("mma.sync.aligned.m16n8k16.row.col.f32.f16.f16.f32 "
                 "{%0,%1,%2,%3}, {%4,%5,%6,%7}, {%8,%9}, {%0,%1,%2,%3};\n"
                 : "+f"(c[0]), "+f"(c[1]), "+f"(c[2]), "+f"(c[3])
                 : "r"(a[0]), "r"(a[1]), "r"(a[2]), "r"(a[3]), "r"(b0), "r"(b1));
}
__device__ __forceinline__ uint32_t ex2h2(float x, float y) {
    __half2 h = __floats2half2_rn(x, y);
    uint32_t in = *(uint32_t*)&h, r;
    asm("ex2.approx.f16x2 %0, %1;\n" : "=r"(r) : "r"(in));
    return r;
}

// ---------------------------------------------------------------------------
// Kernel A: HMMA QKV projection + bias + (Q,K) L2-normalize + fp16 store.
// W -> A fragments (registers), x -> fp16 smem [c][l] read via ldmatrix.trans.
// grid (64, NB, 6), block 256 (8 warps).
// ---------------------------------------------------------------------------
#define XP  72   // xh pitch (halves): 144B rows, 16B aligned, conflict-free ldsm
#define WP  72   // wh pitch
#define SGP 72   // QK staging pitch [l][d=64]
#define VGP 40   // V staging pitch [l][d=32]

__global__ __launch_bounds__(256) void qkvn_kernel(
    const float* __restrict__ x,
    const float* __restrict__ Wq, const float* __restrict__ bq,
    const float* __restrict__ Wk, const float* __restrict__ bk,
    const float* __restrict__ Wv, const float* __restrict__ bv)
{
    __shared__ __align__(16) __half xh[64 * XP];   // [c][l]
    __shared__ __align__(16) __half wh[64 * WP];   // [row][c]
    __shared__ __align__(16) __half stg[64 * SGP]; // [l][d]
    __shared__ float part[4][64];
    __shared__ float scl[64];

    const int lt = blockIdx.x, n = blockIdx.y, z = blockIdx.z;
    const int h = z / 3, sec = z % 3;
    const int nh = n * HEADS + h;
    const int l0 = lt * 64;
    const int tid = threadIdx.x;
    const int warp = tid >> 5, lane = tid & 31;
    const int j = tid & 63, rg = tid >> 6;
    const int m = lane >> 3, rw = lane & 7;
    const int r = lane >> 2, q = lane & 3;

    const float* W; const float* bptr; __half* outh; int rows; bool donorm; float extra;
    if (sec == 0)      { W = Wq + h * DKK * CCH; bptr = bq + h * DKK; outh = Qh + (size_t)nh * LL * DKK; rows = 64; donorm = true;  extra = 1.44269504f; }
    else if (sec == 1) { W = Wk + h * DKK * CCH; bptr = bk + h * DKK; outh = Kh + (size_t)nh * LL * DKK; rows = 64; donorm = true;  extra = 1.0f; }
    else               { W = Wv + h * DVV * CCH; bptr = bv + h * DVV; outh = Vh + (size_t)nh * LL * DVV; rows = 32; donorm = false; extra = 1.0f; }

    // x fp32 -> fp16 smem [c][l]
    #pragma unroll
    for (int t = 0; t < 16; t++) {
        int c = rg + 4 * t;
        xh[c * XP + j] = __float2half_rn(x[((size_t)(n * CCH + c)) * LL + l0 + j]);
    }
    // W fp32 -> fp16 smem [row][c]
    for (int idx = tid; idx < rows * 64; idx += 256)
        wh[(idx >> 6) * WP + (idx & 63)] = __float2half_rn(W[idx]);
    __syncthreads();

    if (rows == 64) {
        const int rowg = warp & 3;   // row group: rows rowg*16..+15
        const int lhalf = warp >> 2; // l half: l lhalf*32..+31

        uint32_t aw[4][4];
        #pragma unroll
        for (int kc = 0; kc < 4; kc++) {
            uint32_t addr = (uint32_t)__cvta_generic_to_shared(
                &wh[(rowg * 16 + (m & 1) * 8 + rw) * WP + kc * 16 + (m >> 1) * 8]);
            ldsm4(aw[kc][0], aw[kc][1], aw[kc][2], aw[kc][3], addr);
        }

        float sacc[4][4] = {};
        #pragma unroll
        for (int kc = 0; kc < 4; kc++) {
            #pragma unroll
            for (int p = 0; p < 2; p++) {
                uint32_t b0, b1, b2, b3;
                uint32_t addr = (uint32_t)__cvta_generic_to_shared(
                    &xh[(kc * 16 + (m & 1) * 8 + rw) * XP + lhalf * 32 + p * 16 + (m >> 1) * 8]);
                ldsm4t(b0, b1, b2, b3, addr);
                mma16816(sacc[2 * p],     aw[kc], b0, b1);
                mma16816(sacc[2 * p + 1], aw[kc], b2, b3);
            }
        }

        // bias
        const float bv0 = bptr[rowg * 16 + r], bv1 = bptr[rowg * 16 + 8 + r];
        #pragma unroll
        for (int nb = 0; nb < 4; nb++) {
            sacc[nb][0] += bv0; sacc[nb][1] += bv0;
            sacc[nb][2] += bv1; sacc[nb][3] += bv1;
        }

        if (donorm) {
            // per-column sum of squares: reduce over 16 rows (lanes xor 4,8,16), then 4 row groups
            float pe[4], po[4];
            #pragma unroll
            for (int nb = 0; nb < 4; nb++) {
                pe[nb] = sacc[nb][0] * sacc[nb][0] + sacc[nb][2] * sacc[nb][2];
                po[nb] = sacc[nb][1] * sacc[nb][1] + sacc[nb][3] * sacc[nb][3];
            }
            #pragma unroll
            for (int s = 4; s <= 16; s <<= 1) {
                #pragma unroll
                for (int nb = 0; nb < 4; nb++) {
                    pe[nb] += __shfl_xor_sync(0xffffffffu, pe[nb], s);
                    po[nb] += __shfl_xor_sync(0xffffffffu, po[nb], s);
                }
            }
            if (r == 0) {
                #pragma unroll
                for (int nb = 0; nb < 4; nb++)
                    *(float2*)&part[rowg][lhalf * 32 + nb * 8 + 2 * q] = make_float2(pe[nb], po[nb]);
            }
            __syncthreads();
            if (tid < 64) {
                float s = part[0][tid] + part[1][tid] + part[2][tid] + part[3][tid];
                scl[tid] = extra / fmaxf(sqrtf(s), 1e-6f);
            }
            __syncthreads();
        }

        // scale + stage [l][d]
        #pragma unroll
        for (int nb = 0; nb < 4; nb++) {
            int lc = lhalf * 32 + nb * 8 + 2 * q;
            float se = donorm ? scl[lc] : 1.0f;
            float so = donorm ? scl[lc + 1] : 1.0f;
            int d0 = rowg * 16 + r, d1 = d0 + 8;
            stg[lc * SGP + d0]       = __float2half_rn(sacc[nb][0] * se);
            stg[(lc + 1) * SGP + d0] = __float2half_rn(sacc[nb][1] * so);
            stg[lc * SGP + d1]       = __float2half_rn(sacc[nb][2] * se);
            stg[(lc + 1) * SGP + d1] = __float2half_rn(sacc[nb][3] * so);
        }
        __syncthreads();

        // coalesced uint4 store: [l][64]
        #pragma unroll
        for (int t = 0; t < 2; t++) {
            int idx = tid + 256 * t;
            int l = idx >> 3, c8 = idx & 7;
            *(uint4*)&outh[(size_t)(l0 + l) * 64 + c8 * 8] = *(uint4*)&stg[l * SGP + c8 * 8];
        }
    } else {
        // V: rows = 32. warp: rowg = warp&1 (16 rows), lq = warp>>1 (16 l)
        const int rowg = warp & 1;
        const int lq = warp >> 1;

        uint32_t aw[4][4];
        #pragma unroll
        for (int kc = 0; kc < 4; kc++) {
            uint32_t addr = (uint32_t)__cvta_generic_to_shared(
                &wh[(rowg * 16 + (m & 1) * 8 + rw) * WP + kc * 16 + (m >> 1) * 8]);
            ldsm4(aw[kc][0], aw[kc][1], aw[kc][2], aw[kc][3], addr);
        }

        float sacc[2][4] = {};
        #pragma unroll
        for (int kc = 0; kc < 4; kc++) {
            uint32_t b0, b1, b2, b3;
            uint32_t addr = (uint32_t)__cvta_generic_to_shared(
                &xh[(kc * 16 + (m & 1) * 8 + rw) * XP + lq * 16 + (m >> 1) * 8]);
            ldsm4t(b0, b1, b2, b3, addr);
            mma16816(sacc[0], aw[kc], b0, b1);
            mma16816(sacc[1], aw[kc], b2, b3);
        }

        const float bv0 = bptr[rowg * 16 + r], bv1 = bptr[rowg * 16 + 8 + r];
        #pragma unroll
        for (int nb = 0; nb < 2; nb++) {
            sacc[nb][0] += bv0; sacc[nb][1] += bv0;
            sacc[nb][2] += bv1; sacc[nb][3] += bv1;
        }

        // stage [l][d] pitch VGP (reuse stg buffer)
        #pragma unroll
        for (int nb = 0; nb < 2; nb++) {
            int lc = lq * 16 + nb * 8 + 2 * q;
            int d0 = rowg * 16 + r, d1 = d0 + 8;
            stg[lc * VGP + d0]       = __float2half_rn(sacc[nb][0]);
            stg[(lc + 1) * VGP + d0] = __float2half_rn(sacc[nb][1]);
            stg[lc * VGP + d1]       = __float2half_rn(sacc[nb][2]);
            stg[(lc + 1) * VGP + d1] = __float2half_rn(sacc[nb][3]);
        }
        __syncthreads();
        {
            int l = tid >> 2, c8 = tid & 3;
            *(uint4*)&outh[(size_t)(l0 + l) * 32 + c8 * 8] = *(uint4*)&stg[l * VGP + c8 * 8];
        }
    }
}

// ---------------------------------------------------------------------------
// Kernel C: HMMA flash attention, split-K over 2 halves of the key range.
// Z computed on the FMA pipe (thread-local fp32, one shuffle at the end).
// grid (32, NH, 2), block 256.
// ---------------------------------------------------------------------------
#define BM 128
#define BN 64
#define QP 72
#define KP 72
#define VPH 40

__global__ __launch_bounds__(256, 2) void attn_kernel()
{
    extern __shared__ __align__(16) char smraw[];
    __half* Qs = (__half*)smraw;            // [128][QP]
    __half* Ks = Qs + BM * QP;              // [64][KP]
    __half* Vs = Ks + BN * KP;              // [64][VPH]

    const int nh = blockIdx.y;
    const int q0 = blockIdx.x * BM;
    const int split = blockIdx.z;
    const int tid = threadIdx.x;
    const int warp = tid >> 5, lane = tid & 31;

    const __half* Qp = Qh + (size_t)nh * LL * DKK;
    const __half* Kp = Kh + (size_t)nh * LL * DKK;
    const __half* Vp = Vh + (size_t)nh * LL * DVV;

    #pragma unroll
    for (int t = 0; t < 4; t++) {
        int idx = tid + 256 * t;
        int row = idx >> 3, c8 = idx & 7;
        *(uint4*)&Qs[row * QP + c8 * 8] = *(const uint4*)&Qp[(size_t)(q0 + row) * 64 + c8 * 8];
    }
    __syncthreads();

    uint32_t aq[4][4];
    {
        const int m = lane >> 3, rw = lane & 7;
        #pragma unroll
        for (int kc = 0; kc < 4; kc++) {
            int row = warp * 16 + (m & 1) * 8 + rw;
            int col = kc * 16 + (m >> 1) * 8;
            uint32_t addr = (uint32_t)__cvta_generic_to_shared(&Qs[row * QP + col]);
            ldsm4(aq[kc][0], aq[kc][1], aq[kc][2], aq[kc][3], addr);
        }
    }

    float oacc[4][4] = {};
    float zlo = 0.f, zhi = 0.f;

    for (int kt = split * KT_PER_SPLIT; kt < (split + 1) * KT_PER_SPLIT; kt++) {
        const int k0 = kt * BN;
        __syncthreads();
        #pragma unroll
        for (int t = 0; t < 2; t++) {
            int idx = tid + 256 * t;
            int row = idx >> 3, c8 = idx & 7;
            *(uint4*)&Ks[row * KP + c8 * 8] = *(const uint4*)&Kp[(size_t)(k0 + row) * 64 + c8 * 8];
        }
        {
            int row = tid >> 2, c8 = tid & 3;
            *(uint4*)&Vs[row * VPH + c8 * 8] = *(const uint4*)&Vp[(size_t)(k0 + row) * 32 + c8 * 8];
        }
        __syncthreads();

        float sacc[8][4] = {};
        {
            const int m = lane >> 3, rw = lane & 7;
            #pragma unroll
            for (int kc = 0; kc < 4; kc++) {
                #pragma unroll
                for (int p = 0; p < 4; p++) {
                    int row = p * 16 + (m >> 1) * 8 + rw;
                    int col = kc * 16 + (m & 1) * 8;
                    uint32_t b0, b1, b2, b3;
                    uint32_t addr = (uint32_t)__cvta_generic_to_shared(&Ks[row * KP + col]);
                    ldsm4(b0, b1, b2, b3, addr);
                    mma16816(sacc[2 * p],     aq[kc], b0, b1);
                    mma16816(sacc[2 * p + 1], aq[kc], b2, b3);
                }
            }
        }

        // P = 2^S packed as A fragments; Z partials on the FMA pipe
        uint32_t ap[4][4];
        #pragma unroll
        for (int t = 0; t < 4; t++) {
            ap[t][0] = ex2h2(sacc[2 * t][0],     sacc[2 * t][1]);
            ap[t][1] = ex2h2(sacc[2 * t][2],     sacc[2 * t][3]);
            ap[t][2] = ex2h2(sacc[2 * t + 1][0], sacc[2 * t + 1][1]);
            ap[t][3] = ex2h2(sacc[2 * t + 1][2], sacc[2 * t + 1][3]);
        }
        #pragma unroll
        for (int t = 0; t < 4; t++) {
            float2 f0 = __half22float2(*(__half2*)&ap[t][0]);
            float2 f1 = __half22float2(*(__half2*)&ap[t][1]);
            float2 f2 = __half22float2(*(__half2*)&ap[t][2]);
            float2 f3 = __half22float2(*(__half2*)&ap[t][3]);
            zlo += (f0.x + f0.y) + (f2.x + f2.y);
            zhi += (f1.x + f1.y) + (f3.x + f3.y);
        }

        {
            const int m = lane >> 3, rw = lane & 7;
            #pragma unroll
            for (int t = 0; t < 4; t++) {
                #pragma unroll
                for (int vb = 0; vb < 2; vb++) {
                    int row = t * 16 + (m & 1) * 8 + rw;
                    int col = vb * 16 + (m >> 1) * 8;
                    uint32_t b0, b1, b2, b3;
                    uint32_t addr = (uint32_t)__cvta_generic_to_shared(&Vs[row * VPH + col]);
                    ldsm4t(b0, b1, b2, b3, addr);
                    mma16816(oacc[2 * vb],     ap[t], b0, b1);
                    mma16816(oacc[2 * vb + 1], ap[t], b2, b3);
                }
            }
        }
    }

    // final Z reduction over the 4 q-lanes
    zlo += __shfl_xor_sync(0xffffffffu, zlo, 1);
    zlo += __shfl_xor_sync(0xffffffffu, zlo, 2);
    zhi += __shfl_xor_sync(0xffffffffu, zhi, 1);
    zhi += __shfl_xor_sync(0xffffffffu, zhi, 2);

    // ---- store unnormalized partials ----
    const int n = nh >> 1, h = nh & 1;
    const int r = lane >> 2, q = lane & 3;
    const int row0 = warp * 16 + r;
    if (q == 0) {
        Zg[((size_t)split * NHH + nh) * LL + q0 + row0]     = zlo;
        Zg[((size_t)split * NHH + nh) * LL + q0 + row0 + 8] = zhi;
    }
    #pragma unroll
    for (int vb = 0; vb < 4; vb++) {
        int dv = vb * 8 + 2 * q;
        int l0v = q0 + row0;
        *(float2*)&Og[((size_t)(split * NB + n) * LL + l0v) * 64 + h * 32 + dv] =
            make_float2(oacc[vb][0], oacc[vb][1]);
        *(float2*)&Og[((size_t)(split * NB + n) * LL + l0v + 8) * 64 + h * 32 + dv] =
            make_float2(oacc[vb][2], oacc[vb][3]);
    }
}

// ---------------------------------------------------------------------------
// Kernel D: split combine + output projection + bias + residual.
// grid (128, NB), block 256.
// ---------------------------------------------------------------------------
__global__ __launch_bounds__(256) void out_kernel(
    const float* __restrict__ x,
    const float* __restrict__ Wm, const float* __restrict__ bm,
    float* __restrict__ out)
{
    __shared__ float Rst[64][33];   // [d][l_local]
    __shared__ float wm[64][64];    // [o][c]
    __shared__ float zinv[2][32];
    const int lt = blockIdx.x, n = blockIdx.y;
    const int l0 = lt * 32;
    const int tid = threadIdx.x;
    const int j = tid & 31, rg = tid >> 5;

    if (tid < 64) {
        int h = tid >> 5, li = tid & 31;
        float z = Zg[((size_t)0 * NHH + n * HEADS + h) * LL + l0 + li]
                + Zg[((size_t)1 * NHH + n * HEADS + h) * LL + l0 + li];
        zinv[h][li] = 1.0f / z;
    }
    #pragma unroll
    for (int t = 0; t < 16; t++) {
        int idx = tid + 256 * t;
        wm[idx >> 6][idx & 63] = Wm[idx];
    }
    __syncthreads();

    #pragma unroll
    for (int t = 0; t < 8; t++) {
        int idx = tid + 256 * t;
        int l = idx >> 6, d = idx & 63;
        float o = Og[((size_t)(0 * NB + n) * LL + l0 + l) * 64 + d]
                + Og[((size_t)(1 * NB + n) * LL + l0 + l) * 64 + d];
        Rst[d][l] = o * zinv[d >> 5][l];
    }
    __syncthreads();

    float accs[8];
    #pragma unroll
    for (int u = 0; u < 8; u++) accs[u] = bm[rg * 8 + u];
    #pragma unroll
    for (int d = 0; d < 64; d++) {
        float rv = Rst[d][j];
        #pragma unroll
        for (int u = 0; u < 8; u++) accs[u] += wm[rg * 8 + u][d] * rv;
    }
    #pragma unroll
    for (int u = 0; u < 8; u++) {
        int c = rg * 8 + u;
        size_t idx = ((size_t)(n * CCH + c)) * LL + l0 + j;
        out[idx] = accs[u] + x[idx];
    }
}

// ---------------------------------------------------------------------------
extern "C" void kernel_launch(void* const* d_in, const int* in_sizes, int n_in,
                              void* d_out, int out_size)
{
    const float* x  = (const float*)d_in[0];
    const float* Wq = (const float*)d_in[1];
    const float* bq = (const float*)d_in[2];
    const float* Wk = (const float*)d_in[3];
    const float* bk = (const float*)d_in[4];
    const float* Wv = (const float*)d_in[5];
    const float* bv = (const float*)d_in[6];
    const float* Wm = (const float*)d_in[7];
    const float* bm = (const float*)d_in[8];
    float* out = (float*)d_out;

    qkvn_kernel<<<dim3(64, NB, 6), 256>>>(x, Wq, bq, Wk, bk, Wv, bv);

    const size_t smB = (size_t)(BM * QP + BN * KP + BN * VPH) * sizeof(__half);
    attn_kernel<<<dim3(LL / BM, NHH, NSPLIT), 256, smB>>>();

    out_kernel<<<dim3(128, NB), 256>>>(x, Wm, bm, out);
}

// round 11
// speedup vs baseline: 7.6670x; 1.0198x over previous
#include <cuda_runtime.h>
#include <cuda_fp16.h>
#include <cstdint>

// Fixed problem shape
#define NB    2
#define CCH   64
#define LL    4096
#define HEADS 2
#define DKK   64
#define DVV   32
#define NHH   4
#define NSPLIT 2
#define KT_PER_SPLIT (LL / 64 / NSPLIT)   // 32

// fp16 activations, l-major: [nh][L][dk]. Q is pre-scaled by log2(e).
__device__ __half Qh[NHH * LL * DKK];
__device__ __half Kh[NHH * LL * DKK];
__device__ __half Vh[NHH * LL * DVV];
__device__ float  Og[NSPLIT * NB * LL * (HEADS * DVV)];  // unnormalized partials
__device__ float  Zg[NSPLIT * NHH * LL];                 // partial row sums

// ---------------------------------------------------------------------------
// PTX helpers
// ---------------------------------------------------------------------------
__device__ __forceinline__ void ldsm4(uint32_t& r0, uint32_t& r1, uint32_t& r2, uint32_t& r3, uint32_t a) {
    asm volatile("ldmatrix.sync.aligned.m8n8.x4.shared.b16 {%0,%1,%2,%3}, [%4];\n"
                 : "=r"(r0), "=r"(r1), "=r"(r2), "=r"(r3) : "r"(a));
}
__device__ __forceinline__ void ldsm4t(uint32_t& r0, uint32_t& r1, uint32_t& r2, uint32_t& r3, uint32_t a) {
    asm volatile("ldmatrix.sync.aligned.m8n8.x4.trans.shared.b16 {%0,%1,%2,%3}, [%4];\n"
                 : "=r"(r0), "=r"(r1), "=r"(r2), "=r"(r3) : "r"(a));
}
__device__ __forceinline__ void mma16816(float* c, const uint32_t* a, uint32_t b0, uint32_t b1) {
    asm volatile("mma.sync.aligned.m16n8k16.row.col.f32.f16.f16.f32 "
                 "{%0,%1,%2,%3}, {%4,%5,%6,%7}, {%8,%9}, {%0,%1,%2,%3};\n"
                 : "+f"(c[0]), "+f"(c[1]), "+f"(c[2]), "+f"(c[3])
                 : "r"(a[0]), "r"(a[1]), "r"(a[2]), "r"(a[3]), "r"(b0), "r"(b1));
}
__device__ __forceinline__ uint32_t ex2h2(float x, float y) {
    __half2 h = __floats2half2_rn(x, y);
    uint32_t in = *(uint32_t*)&h, r;
    asm("ex2.approx.f16x2 %0, %1;\n" : "=r"(r) : "r"(in));
    return r;
}

// ---------------------------------------------------------------------------
// Kernel A: HMMA QKV projection + bias + (Q,K) L2-normalize + fp16 store.
// grid (64, NB, 6), block 256 (8 warps). (unchanged from R9)
// ---------------------------------------------------------------------------
#define XP  72
#define WP  72
#define SGP 72
#define VGP 40

__global__ __launch_bounds__(256) void qkvn_kernel(
    const float* __restrict__ x,
    const float* __restrict__ Wq, const float* __restrict__ bq,
    const float* __restrict__ Wk, const float* __restrict__ bk,
    const float* __restrict__ Wv, const float* __restrict__ bv)
{
    __shared__ __align__(16) __half xh[64 * XP];   // [c][l]
    __shared__ __align__(16) __half wh[64 * WP];   // [row][c]
    __shared__ __align__(16) __half stg[64 * SGP]; // [l][d]
    __shared__ float part[4][64];
    __shared__ float scl[64];

    const int lt = blockIdx.x, n = blockIdx.y, z = blockIdx.z;
    const int h = z / 3, sec = z % 3;
    const int nh = n * HEADS + h;
    const int l0 = lt * 64;
    const int tid = threadIdx.x;
    const int warp = tid >> 5, lane = tid & 31;
    const int j = tid & 63, rg = tid >> 6;
    const int m = lane >> 3, rw = lane & 7;
    const int r = lane >> 2, q = lane & 3;

    const float* W; const float* bptr; __half* outh; int rows; bool donorm; float extra;
    if (sec == 0)      { W = Wq + h * DKK * CCH; bptr = bq + h * DKK; outh = Qh + (size_t)nh * LL * DKK; rows = 64; donorm = true;  extra = 1.44269504f; }
    else if (sec == 1) { W = Wk + h * DKK * CCH; bptr = bk + h * DKK; outh = Kh + (size_t)nh * LL * DKK; rows = 64; donorm = true;  extra = 1.0f; }
    else               { W = Wv + h * DVV * CCH; bptr = bv + h * DVV; outh = Vh + (size_t)nh * LL * DVV; rows = 32; donorm = false; extra = 1.0f; }

    #pragma unroll
    for (int t = 0; t < 16; t++) {
        int c = rg + 4 * t;
        xh[c * XP + j] = __float2half_rn(x[((size_t)(n * CCH + c)) * LL + l0 + j]);
    }
    for (int idx = tid; idx < rows * 64; idx += 256)
        wh[(idx >> 6) * WP + (idx & 63)] = __float2half_rn(W[idx]);
    __syncthreads();

    if (rows == 64) {
        const int rowg = warp & 3;
        const int lhalf = warp >> 2;

        uint32_t aw[4][4];
        #pragma unroll
        for (int kc = 0; kc < 4; kc++) {
            uint32_t addr = (uint32_t)__cvta_generic_to_shared(
                &wh[(rowg * 16 + (m & 1) * 8 + rw) * WP + kc * 16 + (m >> 1) * 8]);
            ldsm4(aw[kc][0], aw[kc][1], aw[kc][2], aw[kc][3], addr);
        }

        float sacc[4][4] = {};
        #pragma unroll
        for (int kc = 0; kc < 4; kc++) {
            #pragma unroll
            for (int p = 0; p < 2; p++) {
                uint32_t b0, b1, b2, b3;
                uint32_t addr = (uint32_t)__cvta_generic_to_shared(
                    &xh[(kc * 16 + (m & 1) * 8 + rw) * XP + lhalf * 32 + p * 16 + (m >> 1) * 8]);
                ldsm4t(b0, b1, b2, b3, addr);
                mma16816(sacc[2 * p],     aw[kc], b0, b1);
                mma16816(sacc[2 * p + 1], aw[kc], b2, b3);
            }
        }

        const float bv0 = bptr[rowg * 16 + r], bv1 = bptr[rowg * 16 + 8 + r];
        #pragma unroll
        for (int nb = 0; nb < 4; nb++) {
            sacc[nb][0] += bv0; sacc[nb][1] += bv0;
            sacc[nb][2] += bv1; sacc[nb][3] += bv1;
        }

        if (donorm) {
            float pe[4], po[4];
            #pragma unroll
            for (int nb = 0; nb < 4; nb++) {
                pe[nb] = sacc[nb][0] * sacc[nb][0] + sacc[nb][2] * sacc[nb][2];
                po[nb] = sacc[nb][1] * sacc[nb][1] + sacc[nb][3] * sacc[nb][3];
            }
            #pragma unroll
            for (int s = 4; s <= 16; s <<= 1) {
                #pragma unroll
                for (int nb = 0; nb < 4; nb++) {
                    pe[nb] += __shfl_xor_sync(0xffffffffu, pe[nb], s);
                    po[nb] += __shfl_xor_sync(0xffffffffu, po[nb], s);
                }
            }
            if (r == 0) {
                #pragma unroll
                for (int nb = 0; nb < 4; nb++)
                    *(float2*)&part[rowg][lhalf * 32 + nb * 8 + 2 * q] = make_float2(pe[nb], po[nb]);
            }
            __syncthreads();
            if (tid < 64) {
                float s = part[0][tid] + part[1][tid] + part[2][tid] + part[3][tid];
                scl[tid] = extra / fmaxf(sqrtf(s), 1e-6f);
            }
            __syncthreads();
        }

        #pragma unroll
        for (int nb = 0; nb < 4; nb++) {
            int lc = lhalf * 32 + nb * 8 + 2 * q;
            float se = donorm ? scl[lc] : 1.0f;
            float so = donorm ? scl[lc + 1] : 1.0f;
            int d0 = rowg * 16 + r, d1 = d0 + 8;
            stg[lc * SGP + d0]       = __float2half_rn(sacc[nb][0] * se);
            stg[(lc + 1) * SGP + d0] = __float2half_rn(sacc[nb][1] * so);
            stg[lc * SGP + d1]       = __float2half_rn(sacc[nb][2] * se);
            stg[(lc + 1) * SGP + d1] = __float2half_rn(sacc[nb][3] * so);
        }
        __syncthreads();

        #pragma unroll
        for (int t = 0; t < 2; t++) {
            int idx = tid + 256 * t;
            int l = idx >> 3, c8 = idx & 7;
            *(uint4*)&outh[(size_t)(l0 + l) * 64 + c8 * 8] = *(uint4*)&stg[l * SGP + c8 * 8];
        }
    } else {
        const int rowg = warp & 1;
        const int lq = warp >> 1;

        uint32_t aw[4][4];
        #pragma unroll
        for (int kc = 0; kc < 4; kc++) {
            uint32_t addr = (uint32_t)__cvta_generic_to_shared(
                &wh[(rowg * 16 + (m & 1) * 8 + rw) * WP + kc * 16 + (m >> 1) * 8]);
            ldsm4(aw[kc][0], aw[kc][1], aw[kc][2], aw[kc][3], addr);
        }

        float sacc[2][4] = {};
        #pragma unroll
        for (int kc = 0; kc < 4; kc++) {
            uint32_t b0, b1, b2, b3;
            uint32_t addr = (uint32_t)__cvta_generic_to_shared(
                &xh[(kc * 16 + (m & 1) * 8 + rw) * XP + lq * 16 + (m >> 1) * 8]);
            ldsm4t(b0, b1, b2, b3, addr);
            mma16816(sacc[0], aw[kc], b0, b1);
            mma16816(sacc[1], aw[kc], b2, b3);
        }

        const float bv0 = bptr[rowg * 16 + r], bv1 = bptr[rowg * 16 + 8 + r];
        #pragma unroll
        for (int nb = 0; nb < 2; nb++) {
            sacc[nb][0] += bv0; sacc[nb][1] += bv0;
            sacc[nb][2] += bv1; sacc[nb][3] += bv1;
        }

        #pragma unroll
        for (int nb = 0; nb < 2; nb++) {
            int lc = lq * 16 + nb * 8 + 2 * q;
            int d0 = rowg * 16 + r, d1 = d0 + 8;
            stg[lc * VGP + d0]       = __float2half_rn(sacc[nb][0]);
            stg[(lc + 1) * VGP + d0] = __float2half_rn(sacc[nb][1]);
            stg[lc * VGP + d1]       = __float2half_rn(sacc[nb][2]);
            stg[(lc + 1) * VGP + d1] = __float2half_rn(sacc[nb][3]);
        }
        __syncthreads();
        {
            int l = tid >> 2, c8 = tid & 3;
            *(uint4*)&outh[(size_t)(l0 + l) * 32 + c8 * 8] = *(uint4*)&stg[l * VGP + c8 * 8];
        }
    }
}

// ---------------------------------------------------------------------------
// Kernel C: HMMA flash attention, split-K, 2D warp tiling (qg x kh),
// double-buffered K/V with one sync per iteration.
// Warp (qg,kh): 32 q-rows (qg*32..), 32 keys (kh*32..) of each 64-key tile.
// Cross-warp O/Z combine over kh at the end via smem staging.
// grid (32, NH, 2), block 256.
// ---------------------------------------------------------------------------
#define BM 128
#define BN 64
#define QP 72
#define KP 72
#define VPH 40
#define RP 34   // reduction staging pitch (floats); EVEN so float2 accesses stay 8B-aligned

__global__ __launch_bounds__(256, 2) void attn_kernel()
{
    extern __shared__ __align__(16) char smraw[];
    __half* Qs  = (__half*)smraw;            // [128][QP]
    __half* Ks0 = Qs + BM * QP;              // [64][KP] buf0
    __half* Ks1 = Ks0 + BN * KP;             // [64][KP] buf1
    __half* Vs0 = Ks1 + BN * KP;             // [64][VPH] buf0
    __half* Vs1 = Vs0 + BN * VPH;            // [64][VPH] buf1
    float* red  = (float*)Ks0;               // post-loop: [128][RP]
    float* zred = red + BM * RP;             // [128]

    const int nh = blockIdx.y;
    const int q0 = blockIdx.x * BM;
    const int split = blockIdx.z;
    const int tid = threadIdx.x;
    const int warp = tid >> 5, lane = tid & 31;
    const int qg = warp >> 1, kh = warp & 1;
    const int m = lane >> 3, rw = lane & 7;
    const int r = lane >> 2, q = lane & 3;

    const __half* Qp = Qh + (size_t)nh * LL * DKK;
    const __half* Kp = Kh + (size_t)nh * LL * DKK;
    const __half* Vp = Vh + (size_t)nh * LL * DVV;

    // load Q tile + first K/V tile
    #pragma unroll
    for (int t = 0; t < 4; t++) {
        int idx = tid + 256 * t;
        int row = idx >> 3, c8 = idx & 7;
        *(uint4*)&Qs[row * QP + c8 * 8] = *(const uint4*)&Qp[(size_t)(q0 + row) * 64 + c8 * 8];
    }
    {
        const int k0 = split * KT_PER_SPLIT * BN;
        #pragma unroll
        for (int t = 0; t < 2; t++) {
            int idx = tid + 256 * t;
            int row = idx >> 3, c8 = idx & 7;
            *(uint4*)&Ks0[row * KP + c8 * 8] = *(const uint4*)&Kp[(size_t)(k0 + row) * 64 + c8 * 8];
        }
        int row = tid >> 2, c8 = tid & 3;
        *(uint4*)&Vs0[row * VPH + c8 * 8] = *(const uint4*)&Vp[(size_t)(k0 + row) * 32 + c8 * 8];
    }
    __syncthreads();

    // loop-invariant Q fragments: 32 rows (2 x m16) x 64 dk (4 x k16)
    uint32_t aq[2][2][4][4];
    #pragma unroll
    for (int mq = 0; mq < 2; mq++) {
        #pragma unroll
        for (int kc = 0; kc < 4; kc++) {
            int row = qg * 32 + mq * 16 + (m & 1) * 8 + rw;
            int col = kc * 16 + (m >> 1) * 8;
            uint32_t addr = (uint32_t)__cvta_generic_to_shared(&Qs[row * QP + col]);
            ldsm4(aq[mq][0][kc][0], aq[mq][0][kc][1], aq[mq][0][kc][2], aq[mq][0][kc][3], addr);
        }
    }

    float oacc[2][4][4] = {};   // [mq][dv n8 block][frag]
    float zlo[2] = {0.f, 0.f}, zhi[2] = {0.f, 0.f};

    for (int i = 0; i < KT_PER_SPLIT; i++) {
        if (i) __syncthreads();
        const __half* Kb = (i & 1) ? Ks1 : Ks0;
        const __half* Vb = (i & 1) ? Vs1 : Vs0;
        __half* Kn = (i & 1) ? Ks0 : Ks1;
        __half* Vn = (i & 1) ? Vs0 : Vs1;

        // prefetch next tile into registers (latency overlapped with compute)
        uint4 pk0, pk1, pv;
        const bool havenext = (i + 1 < KT_PER_SPLIT);
        if (havenext) {
            const int k0n = (split * KT_PER_SPLIT + i + 1) * BN;
            {
                int row = tid >> 3, c8 = tid & 7;
                pk0 = *(const uint4*)&Kp[(size_t)(k0n + row) * 64 + c8 * 8];
            }
            {
                int idx = tid + 256;
                int row = idx >> 3, c8 = idx & 7;
                pk1 = *(const uint4*)&Kp[(size_t)(k0n + row) * 64 + c8 * 8];
            }
            {
                int row = tid >> 2, c8 = tid & 3;
                pv = *(const uint4*)&Vp[(size_t)(k0n + row) * 32 + c8 * 8];
            }
        }

        // ---- S = Q K^T : 32q x 32k (keys kh*32..+31) ----
        float sacc[2][4][4] = {};
        #pragma unroll
        for (int kc = 0; kc < 4; kc++) {
            #pragma unroll
            for (int p = 0; p < 2; p++) {
                int row = kh * 32 + p * 16 + (m >> 1) * 8 + rw;
                int col = kc * 16 + (m & 1) * 8;
                uint32_t b0, b1, b2, b3;
                uint32_t addr = (uint32_t)__cvta_generic_to_shared(&Kb[row * KP + col]);
                ldsm4(b0, b1, b2, b3, addr);
                #pragma unroll
                for (int mq = 0; mq < 2; mq++) {
                    mma16816(sacc[mq][2 * p],     aq[mq][0][kc], b0, b1);
                    mma16816(sacc[mq][2 * p + 1], aq[mq][0][kc], b2, b3);
                }
            }
        }

        // ---- P = 2^S packed as A fragments; Z on the FMA pipe ----
        uint32_t ap[2][2][4];
        #pragma unroll
        for (int mq = 0; mq < 2; mq++) {
            #pragma unroll
            for (int p = 0; p < 2; p++) {
                ap[mq][p][0] = ex2h2(sacc[mq][2 * p][0],     sacc[mq][2 * p][1]);
                ap[mq][p][1] = ex2h2(sacc[mq][2 * p][2],     sacc[mq][2 * p][3]);
                ap[mq][p][2] = ex2h2(sacc[mq][2 * p + 1][0], sacc[mq][2 * p + 1][1]);
                ap[mq][p][3] = ex2h2(sacc[mq][2 * p + 1][2], sacc[mq][2 * p + 1][3]);
            }
        }
        #pragma unroll
        for (int mq = 0; mq < 2; mq++) {
            #pragma unroll
            for (int p = 0; p < 2; p++) {
                float2 f0 = __half22float2(*(__half2*)&ap[mq][p][0]);
                float2 f1 = __half22float2(*(__half2*)&ap[mq][p][1]);
                float2 f2 = __half22float2(*(__half2*)&ap[mq][p][2]);
                float2 f3 = __half22float2(*(__half2*)&ap[mq][p][3]);
                zlo[mq] += (f0.x + f0.y) + (f2.x + f2.y);
                zhi[mq] += (f1.x + f1.y) + (f3.x + f3.y);
            }
        }

        // ---- O += P V : 32q x 32dv over this warp's 32 keys ----
        #pragma unroll
        for (int p = 0; p < 2; p++) {
            #pragma unroll
            for (int vb = 0; vb < 2; vb++) {
                int row = kh * 32 + p * 16 + (m & 1) * 8 + rw;
                int col = vb * 16 + (m >> 1) * 8;
                uint32_t b0, b1, b2, b3;
                uint32_t addr = (uint32_t)__cvta_generic_to_shared(&Vb[row * VPH + col]);
                ldsm4t(b0, b1, b2, b3, addr);
                #pragma unroll
                for (int mq = 0; mq < 2; mq++) {
                    mma16816(oacc[mq][2 * vb],     ap[mq][p], b0, b1);
                    mma16816(oacc[mq][2 * vb + 1], ap[mq][p], b2, b3);
                }
            }
        }

        // store prefetched tile into the other buffer
        if (havenext) {
            {
                int row = tid >> 3, c8 = tid & 7;
                *(uint4*)&Kn[row * KP + c8 * 8] = pk0;
            }
            {
                int idx = tid + 256;
                int row = idx >> 3, c8 = idx & 7;
                *(uint4*)&Kn[row * KP + c8 * 8] = pk1;
            }
            {
                int row = tid >> 2, c8 = tid & 3;
                *(uint4*)&Vn[row * VPH + c8 * 8] = pv;
            }
        }
    }

    // Z lane reduction over the 4 q-lanes
    #pragma unroll
    for (int mq = 0; mq < 2; mq++) {
        zlo[mq] += __shfl_xor_sync(0xffffffffu, zlo[mq], 1);
        zlo[mq] += __shfl_xor_sync(0xffffffffu, zlo[mq], 2);
        zhi[mq] += __shfl_xor_sync(0xffffffffu, zhi[mq], 1);
        zhi[mq] += __shfl_xor_sync(0xffffffffu, zhi[mq], 2);
    }

    // ---- cross-warp (kh) combine via smem, then store partials ----
    __syncthreads();   // all compute done; Ks/Vs reusable as staging
    if (kh == 1) {
        #pragma unroll
        for (int mq = 0; mq < 2; mq++) {
            int row = qg * 32 + mq * 16 + r;
            #pragma unroll
            for (int nb = 0; nb < 4; nb++) {
                *(float2*)&red[row * RP + nb * 8 + 2 * q] =
                    make_float2(oacc[mq][nb][0], oacc[mq][nb][1]);
                *(float2*)&red[(row + 8) * RP + nb * 8 + 2 * q] =
                    make_float2(oacc[mq][nb][2], oacc[mq][nb][3]);
            }
            if (q == 0) {
                zred[row]     = zlo[mq];
                zred[row + 8] = zhi[mq];
            }
        }
    }
    __syncthreads();
    if (kh == 0) {
        const int n = nh >> 1, h = nh & 1;
        #pragma unroll
        for (int mq = 0; mq < 2; mq++) {
            int row = qg * 32 + mq * 16 + r;
            if (q == 0) {
                Zg[((size_t)split * NHH + nh) * LL + q0 + row]     = zlo[mq] + zred[row];
                Zg[((size_t)split * NHH + nh) * LL + q0 + row + 8] = zhi[mq] + zred[row + 8];
            }
            #pragma unroll
            for (int nb = 0; nb < 4; nb++) {
                int dv = nb * 8 + 2 * q;
                float2 r0 = *(float2*)&red[row * RP + dv];
                float2 r1 = *(float2*)&red[(row + 8) * RP + dv];
                *(float2*)&Og[((size_t)(split * NB + n) * LL + q0 + row) * 64 + h * 32 + dv] =
                    make_float2(oacc[mq][nb][0] + r0.x, oacc[mq][nb][1] + r0.y);
                *(float2*)&Og[((size_t)(split * NB + n) * LL + q0 + row + 8) * 64 + h * 32 + dv] =
                    make_float2(oacc[mq][nb][2] + r1.x, oacc[mq][nb][3] + r1.y);
            }
        }
    }
}

// ---------------------------------------------------------------------------
// Kernel D: split combine + output projection + bias + residual.
// grid (128, NB), block 256. (unchanged from R9)
// ---------------------------------------------------------------------------
__global__ __launch_bounds__(256) void out_kernel(
    const float* __restrict__ x,
    const float* __restrict__ Wm, const float* __restrict__ bm,
    float* __restrict__ out)
{
    __shared__ float Rst[64][33];
    __shared__ float wm[64][64];
    __shared__ float zinv[2][32];
    const int lt = blockIdx.x, n = blockIdx.y;
    const int l0 = lt * 32;
    const int tid = threadIdx.x;
    const int j = tid & 31, rg = tid >> 5;

    if (tid < 64) {
        int h = tid >> 5, li = tid & 31;
        float z = Zg[((size_t)0 * NHH + n * HEADS + h) * LL + l0 + li]
                + Zg[((size_t)1 * NHH + n * HEADS + h) * LL + l0 + li];
        zinv[h][li] = 1.0f / z;
    }
    #pragma unroll
    for (int t = 0; t < 16; t++) {
        int idx = tid + 256 * t;
        wm[idx >> 6][idx & 63] = Wm[idx];
    }
    __syncthreads();

    #pragma unroll
    for (int t = 0; t < 8; t++) {
        int idx = tid + 256 * t;
        int l = idx >> 6, d = idx & 63;
        float o = Og[((size_t)(0 * NB + n) * LL + l0 + l) * 64 + d]
                + Og[((size_t)(1 * NB + n) * LL + l0 + l) * 64 + d];
        Rst[d][l] = o * zinv[d >> 5][l];
    }
    __syncthreads();

    float accs[8];
    #pragma unroll
    for (int u = 0; u < 8; u++) accs[u] = bm[rg * 8 + u];
    #pragma unroll
    for (int d = 0; d < 64; d++) {
        float rv = Rst[d][j];
        #pragma unroll
        for (int u = 0; u < 8; u++) accs[u] += wm[rg * 8 + u][d] * rv;
    }
    #pragma unroll
    for (int u = 0; u < 8; u++) {
        int c = rg * 8 + u;
        size_t idx = ((size_t)(n * CCH + c)) * LL + l0 + j;
        out[idx] = accs[u] + x[idx];
    }
}

// ---------------------------------------------------------------------------
extern "C" void kernel_launch(void* const* d_in, const int* in_sizes, int n_in,
                              void* d_out, int out_size)
{
    const float* x  = (const float*)d_in[0];
    const float* Wq = (const float*)d_in[1];
    const float* bq = (const float*)d_in[2];
    const float* Wk = (const float*)d_in[3];
    const float* bk = (const float*)d_in[4];
    const float* Wv = (const float*)d_in[5];
    const float* bv = (const float*)d_in[6];
    const float* Wm = (const float*)d_in[7];
    const float* bm = (const float*)d_in[8];
    float* out = (float*)d_out;

    qkvn_kernel<<<dim3(64, NB, 6), 256>>>(x, Wq, bq, Wk, bk, Wv, bv);

    const size_t smB = (size_t)(BM * QP + 2 * BN * KP + 2 * BN * VPH) * sizeof(__half);
    attn_kernel<<<dim3(LL / BM, NHH, NSPLIT), 256, smB>>>();

    out_kernel<<<dim3(128, NB), 256>>>(x, Wm, bm, out);
}